// round 1
// baseline (speedup 1.0000x reference)
#include <cuda_runtime.h>
#include <math.h>
#include <stddef.h>

#define NN    100000
#define EHID  300
#define NE1   400000
#define NE2   800000
#define RRN   2000
#define RHD   100
#define LGEN  60000
#define NEGS  0.01f
#define OUTW  800

// ---------------- device scratch (static allocation; no cudaMalloc) ----------------
static __device__ float g_xw [(size_t)NN * EHID];   // GEMM outputs (xw / gate), reused
static __device__ float g_agg[(size_t)NN * EHID];   // aggregation accumulator
static __device__ float g_x  [(size_t)NN * EHID];   // current node features (300)
static __device__ float g_dinv[NN];
static __device__ int   g_deg [NN];
static __device__ float g_m1[NN], g_s1[NN], g_m2[NN], g_s2[NN];
static __device__ float g_na[NN], g_nb[NN];         // per-node dot products
static __device__ float g_e1[NE2];                  // per-edge scratch (gat / g2e-h)
static __device__ float g_e2[NE1];                  // per-edge scratch (g2e-t)
static __device__ float g_rmerge[RRN * RHD], g_rtri[RRN * RHD];
static __device__ float g_xr[RRN * RHD], g_rgate[RRN * RHD];
static __device__ float g_rm[3 * RRN], g_rs[3 * RRN];
static __device__ float g_lt[LGEN], g_lp[LGEN];
static __device__ float g_rcar[RRN];

// ---------------- device helpers ----------------
__device__ __forceinline__ void atomicMaxF(float* a, float v) {
    // monotonic int/uint trick; works for mixed signs; init must be -inf
    if (v >= 0.f) atomicMax((int*)a, __float_as_int(v));
    else          atomicMin((unsigned int*)a, __float_as_uint(v));
}

__device__ __forceinline__ void redAdd4(float* a, float x, float y, float z, float w) {
    asm volatile("red.global.add.v4.f32 [%0], {%1,%2,%3,%4};"
                 :: "l"(a), "f"(x), "f"(y), "f"(z), "f"(w) : "memory");
}

__device__ __forceinline__ float warpSum(float v) {
    #pragma unroll
    for (int o = 16; o; o >>= 1) v += __shfl_xor_sync(0xffffffffu, v, o);
    return v;
}

__device__ __forceinline__ float lrelu(float v) { return v > 0.f ? v : NEGS * v; }
__device__ __forceinline__ float sigf(float z)  { return 1.f / (1.f + expf(-z)); }

// ---------------- GEMM: Out[M,OC] = A[M,K] @ W[OC,K]^T  (both K-major) ----------------
// 64x64 tile, full K resident in smem, 4x4 register blocking, 256 threads.
__global__ void k_gemm(const float* __restrict__ A, const float* __restrict__ W,
                       float* __restrict__ Out, int M, int K, int OC) {
    extern __shared__ float sm[];
    float* As = sm;            // [64][K]
    float* Ws = sm + 64 * K;   // [64][K]
    const int n0 = blockIdx.x * 64, o0 = blockIdx.y * 64;
    const int tid = threadIdx.x;
    const int Kv4 = K >> 2;

    for (int idx = tid; idx < 64 * Kv4; idx += 256) {
        int r = idx / Kv4, k4 = idx - r * Kv4;
        float4 v = make_float4(0.f, 0.f, 0.f, 0.f);
        if (n0 + r < M) v = *(const float4*)&A[(size_t)(n0 + r) * K + k4 * 4];
        *(float4*)&As[r * K + k4 * 4] = v;
    }
    for (int idx = tid; idx < 64 * Kv4; idx += 256) {
        int r = idx / Kv4, k4 = idx - r * Kv4;
        float4 v = make_float4(0.f, 0.f, 0.f, 0.f);
        if (o0 + r < OC) v = *(const float4*)&W[(size_t)(o0 + r) * K + k4 * 4];
        *(float4*)&Ws[r * K + k4 * 4] = v;
    }
    __syncthreads();

    const int tx = tid & 15, ty = tid >> 4;
    const float* Ap = &As[(ty * 4) * K];
    const float* Wp = &Ws[(tx * 4) * K];
    float acc[4][4] = {};
    #pragma unroll 4
    for (int k = 0; k < K; k++) {
        float a0 = Ap[k], a1 = Ap[K + k], a2 = Ap[2 * K + k], a3 = Ap[3 * K + k];
        float w0 = Wp[k], w1 = Wp[K + k], w2 = Wp[2 * K + k], w3 = Wp[3 * K + k];
        acc[0][0] += a0 * w0; acc[0][1] += a0 * w1; acc[0][2] += a0 * w2; acc[0][3] += a0 * w3;
        acc[1][0] += a1 * w0; acc[1][1] += a1 * w1; acc[1][2] += a1 * w2; acc[1][3] += a1 * w3;
        acc[2][0] += a2 * w0; acc[2][1] += a2 * w1; acc[2][2] += a2 * w2; acc[2][3] += a2 * w3;
        acc[3][0] += a3 * w0; acc[3][1] += a3 * w1; acc[3][2] += a3 * w2; acc[3][3] += a3 * w3;
    }
    #pragma unroll
    for (int q = 0; q < 4; q++) {
        int row = n0 + ty * 4 + q;
        if (row >= M) continue;
        #pragma unroll
        for (int p = 0; p < 4; p++) {
            int col = o0 + tx * 4 + p;
            if (col < OC) Out[(size_t)row * OC + col] = acc[q][p];
        }
    }
}

// ---------------- small utility kernels ----------------
__global__ void k_fill_ms(float* m, float* s, int n) {
    int i = blockIdx.x * 256 + threadIdx.x;
    if (i < n) { m[i] = __int_as_float(0xff800000); s[i] = 0.f; }
}
__global__ void k_relu(float* p, int n) {
    int i = blockIdx.x * 256 + threadIdx.x;
    if (i < n) p[i] = fmaxf(p[i], 0.f);
}
__global__ void k_deg(const int* __restrict__ ei, int nE, int* __restrict__ deg) {
    int e = blockIdx.x * 256 + threadIdx.x;
    if (e < nE) atomicAdd(&deg[ei[e]], 1);
}
__global__ void k_dinv(const int* __restrict__ deg, float* __restrict__ dinv, int n) {
    int i = blockIdx.x * 256 + threadIdx.x;
    if (i < n) { int d = deg[i]; dinv[i] = d > 0 ? rsqrtf((float)d) : 0.f; }
}

// ---------------- GCN edge aggregation: agg[i] += dinv[j]*dinv[i]*xw[j] ----------------
__global__ void k_gcn_agg(const int* __restrict__ ej, const int* __restrict__ ei,
                          const float* __restrict__ dinv, const float* __restrict__ xw,
                          float* __restrict__ agg, int nE) {
    int w = (blockIdx.x * blockDim.x + threadIdx.x) >> 5;
    int lane = threadIdx.x & 31;
    if (w >= nE) return;
    int j = ej[w], i = ei[w];
    float norm = dinv[j] * dinv[i];
    const float4* src = (const float4*)&xw[(size_t)j * EHID];
    float* dst = &agg[(size_t)i * EHID];
    for (int c4 = lane; c4 < EHID / 4; c4 += 32) {
        float4 v = src[c4];
        redAdd4(dst + c4 * 4, norm * v.x, norm * v.y, norm * v.z, norm * v.w);
    }
}

// ---------------- highway (big): out = sig(gate+b)*relu(agg) + (1-sig)*x1 ----------------
__global__ void k_highway_big(const float* __restrict__ gate, const float* __restrict__ bias,
                              const float* __restrict__ x1, const float* __restrict__ agg,
                              float* __restrict__ xout, float* __restrict__ dout) {
    int idx = blockIdx.x * 256 + threadIdx.x;
    if (idx >= NN * EHID) return;
    int c = idx % EHID;
    float g = sigf(gate[idx] + bias[c]);
    float a = fmaxf(agg[idx], 0.f);
    float v = g * a + (1.f - g) * x1[idx];
    xout[idx] = v;
    if (dout) { int n = idx / EHID; dout[(size_t)n * OUTW + c] = v; }
}

__global__ void k_highway_r(const float* __restrict__ gate, const float* __restrict__ bias,
                            const float* __restrict__ x1, const float* __restrict__ x2,
                            float* __restrict__ out, int n, int C) {
    int idx = blockIdx.x * 256 + threadIdx.x;
    if (idx >= n * C) return;
    int c = idx % C;
    float g = sigf(gate[idx] + bias[c]);
    out[idx] = g * x2[idx] + (1.f - g) * x1[idx];
}

// ---------------- l_gat passes (R=2000 segments, LGE edges) ----------------
__global__ void k_lgat_p1(const int* __restrict__ ej, const int* __restrict__ ei,
                          const float* __restrict__ val, float* mi, float* mj, int nE) {
    int e = blockIdx.x * 256 + threadIdx.x;
    if (e >= nE) return;
    float v = val[e];
    atomicMaxF(&mi[ei[e]], v);
    atomicMaxF(&mj[ej[e]], v);
}
__global__ void k_lgat_p2(const int* __restrict__ ej, const int* __restrict__ ei,
                          const float* __restrict__ val, const float* __restrict__ mi,
                          const float* __restrict__ mj, float* si, float* sj, int nE) {
    int e = blockIdx.x * 256 + threadIdx.x;
    if (e >= nE) return;
    float v = val[e];
    atomicAdd(&si[ei[e]], expf(v - mi[ei[e]]));
    atomicAdd(&sj[ej[e]], expf(v - mj[ej[e]]));
}
__global__ void k_lgat_p3(const int* __restrict__ ej, const int* __restrict__ ei,
                          const float* __restrict__ val,
                          const float* __restrict__ mi, const float* __restrict__ si,
                          const float* __restrict__ mj, const float* __restrict__ sj,
                          float* m3, float* tbuf, int nE) {
    int e = blockIdx.x * 256 + threadIdx.x;
    if (e >= nE) return;
    int i = ei[e], j = ej[e];
    float v = val[e];
    float vi = expf(v - mi[i]) / (si[i] + 1e-16f);
    float vj = expf(v - mj[j]) / (sj[j] + 1e-16f);
    float t = vi + vj;
    tbuf[e] = t;
    atomicMaxF(&m3[j], t);
}
__global__ void k_lgat_p4(const int* __restrict__ ej, const float* __restrict__ tbuf,
                          const float* __restrict__ m3, float* s3, float* pbuf, int nE) {
    int e = blockIdx.x * 256 + threadIdx.x;
    if (e >= nE) return;
    float p = expf(tbuf[e] - m3[ej[e]]);
    pbuf[e] = p;
    atomicAdd(&s3[ej[e]], p);
}
__global__ void k_lgat_p5(const int* __restrict__ ej, const int* __restrict__ ei,
                          const float* __restrict__ pbuf, const float* __restrict__ s3,
                          const float* __restrict__ x, float* __restrict__ outb, int nE) {
    int w = (blockIdx.x * blockDim.x + threadIdx.x) >> 5;
    int lane = threadIdx.x & 31;
    if (w >= nE) return;
    int j = ej[w], i = ei[w];
    float alpha = pbuf[w] / (s3[j] + 1e-16f);
    if (lane < RHD / 4) {
        float4 v = ((const float4*)&x[(size_t)j * RHD])[lane];
        redAdd4(&outb[(size_t)i * RHD + lane * 4], alpha * v.x, alpha * v.y, alpha * v.z, alpha * v.w);
    }
}

// ---------------- per-node / per-row dot products ----------------
__global__ void k_node_dots2(const float* __restrict__ X, int stride, int len,
                             const float* __restrict__ va, const float* __restrict__ vb,
                             float* __restrict__ oa, float* __restrict__ ob, int n) {
    int w = (blockIdx.x * blockDim.x + threadIdx.x) >> 5;
    int lane = threadIdx.x & 31;
    if (w >= n) return;
    const float* row = X + (size_t)w * stride;
    float sa = 0.f, sb = 0.f;
    for (int c = lane; c < len; c += 32) { float x = row[c]; sa += x * va[c]; sb += x * vb[c]; }
    sa = warpSum(sa); sb = warpSum(sb);
    if (lane == 0) { oa[w] = sa; ob[w] = sb; }
}
__global__ void k_dot_rows(const float* __restrict__ X, int stride, int len,
                           const float* __restrict__ v, float* __restrict__ out, int n) {
    int w = (blockIdx.x * blockDim.x + threadIdx.x) >> 5;
    int lane = threadIdx.x & 31;
    if (w >= n) return;
    const float* row = X + (size_t)w * stride;
    float s = 0.f;
    for (int c = lane; c < len; c += 32) s += row[c] * v[c];
    s = warpSum(s);
    if (lane == 0) out[w] = s;
}
// rcar[r] = dot(rel_merge[r], ar[0:100]) + dot(rel_tri[r], ar[100:200])
__global__ void k_rcar(const float* __restrict__ mrg, const float* __restrict__ tri,
                       const float* __restrict__ ar, float* __restrict__ rcar) {
    int w = (blockIdx.x * blockDim.x + threadIdx.x) >> 5;
    int lane = threadIdx.x & 31;
    if (w >= RRN) return;
    float s = 0.f;
    for (int c = lane; c < RHD; c += 32)
        s += mrg[(size_t)w * RHD + c] * ar[c] + tri[(size_t)w * RHD + c] * ar[RHD + c];
    s = warpSum(s);
    if (lane == 0) rcar[w] = s;
}

// ---------------- GAT over edge_index_all ----------------
__global__ void k_gat_p1(const int* __restrict__ ej, const int* __restrict__ ei,
                         const int* __restrict__ ra, const float* __restrict__ xa,
                         const float* __restrict__ xb, const float* __restrict__ rcar,
                         float* __restrict__ ebuf, float* m, int nE) {
    int e = blockIdx.x * 256 + threadIdx.x;
    if (e >= nE) return;
    int i = ei[e], j = ej[e];
    int rr = ra[e]; if (rr >= RRN) rr -= RRN;     // rel_emb rows duplicated
    float v = lrelu(xa[i] + xb[j] + rcar[rr]);
    ebuf[e] = v;
    atomicMaxF(&m[i], v);
}
// generic: p = exp(e - m[idx]); e := p; s[idx] += p
__global__ void k_seg_exp(const int* __restrict__ idx, float* __restrict__ ebuf,
                          const float* __restrict__ m, float* s, int nE) {
    int e = blockIdx.x * 256 + threadIdx.x;
    if (e >= nE) return;
    int g = idx[e];
    float p = expf(ebuf[e] - m[g]);
    ebuf[e] = p;
    atomicAdd(&s[g], p);
}
__global__ void k_gat_p3(const int* __restrict__ ej, const int* __restrict__ ei,
                         const float* __restrict__ pbuf, const float* __restrict__ s,
                         const float* __restrict__ x, float* __restrict__ agg, int nE) {
    int w = (blockIdx.x * blockDim.x + threadIdx.x) >> 5;
    int lane = threadIdx.x & 31;
    if (w >= nE) return;
    int j = ej[w], i = ei[w];
    float alpha = pbuf[w] / (s[i] + 1e-16f);
    const float4* src = (const float4*)&x[(size_t)j * EHID];
    float* dst = &agg[(size_t)i * EHID];
    for (int c4 = lane; c4 < EHID / 4; c4 += 32) {
        float4 v = src[c4];
        redAdd4(dst + c4 * 4, alpha * v.x, alpha * v.y, alpha * v.z, alpha * v.w);
    }
}
// write d_out[:,300:600] = relu(agg), zero d_out[:,600:800]
__global__ void k_concat_gat(const float* __restrict__ agg, float* __restrict__ out) {
    int idx = blockIdx.x * 256 + threadIdx.x;
    if (idx >= NN * EHID) return;
    int n = idx / EHID, c = idx - n * EHID;
    out[(size_t)n * OUTW + 300 + c] = fmaxf(agg[idx], 0.f);
    if (c < 200) out[(size_t)n * OUTW + 600 + c] = 0.f;
}

// ---------------- gat_r_to_e ----------------
__global__ void k_g2e_p1(const int* __restrict__ eh, const int* __restrict__ et,
                         const int* __restrict__ rel, const float* __restrict__ xh,
                         const float* __restrict__ xt, const float* __restrict__ er,
                         float* __restrict__ e1, float* __restrict__ e2,
                         float* m1, float* m2, int nE) {
    int e = blockIdx.x * 256 + threadIdx.x;
    if (e >= nE) return;
    int h = eh[e], t = et[e], r = rel[e];
    float w = er[r];
    float a = lrelu(xh[h] + w);
    float b = lrelu(xt[t] + w);
    e1[e] = a; e2[e] = b;
    atomicMaxF(&m1[h], a);
    atomicMaxF(&m2[t], b);
}
__global__ void k_g2e_p3(const int* __restrict__ eh, const int* __restrict__ et,
                         const int* __restrict__ rel,
                         const float* __restrict__ p1, const float* __restrict__ s1,
                         const float* __restrict__ p2, const float* __restrict__ s2,
                         const float* __restrict__ xr, float* __restrict__ out, int nE) {
    int w = (blockIdx.x * blockDim.x + threadIdx.x) >> 5;
    int lane = threadIdx.x & 31;
    if (w >= nE) return;
    int h = eh[w], t = et[w], r = rel[w];
    float a1 = p1[w] / (s1[h] + 1e-16f);
    float a2 = p2[w] / (s2[t] + 1e-16f);
    if (lane < RHD / 4) {
        float4 v = ((const float4*)&xr[(size_t)r * RHD])[lane];
        redAdd4(&out[(size_t)h * OUTW + 600 + lane * 4], a1 * v.x, a1 * v.y, a1 * v.z, a1 * v.w);
        redAdd4(&out[(size_t)t * OUTW + 700 + lane * 4], a2 * v.x, a2 * v.y, a2 * v.z, a2 * v.w);
    }
}

// ---------------- host ----------------
static inline int TPE(int n) { return (n + 255) / 256; }   // thread-per-element grid
static inline int WPE(int n) { return (n + 7) / 8; }       // warp-per-element grid (256 thr)

extern "C" void kernel_launch(void* const* d_in, const int* in_sizes, int n_in,
                              void* d_out_v, int out_size) {
    const float* x_e       = (const float*)d_in[0];
    const float* merge_val = (const float*)d_in[1];
    const float* tri_val   = (const float*)d_in[2];
    const float* gcn1_w    = (const float*)d_in[3];
    const float* hw1_w     = (const float*)d_in[4];
    const float* hw1_b     = (const float*)d_in[5];
    const float* gcn2_w    = (const float*)d_in[6];
    const float* hw2_w     = (const float*)d_in[7];
    const float* hw2_b     = (const float*)d_in[8];
    const float* rel_out1  = (const float*)d_in[9];
    const float* rel_tri1  = (const float*)d_in[10];
    const float* hwr_w     = (const float*)d_in[11];
    const float* hwr_b     = (const float*)d_in[12];
    const float* gat_ai    = (const float*)d_in[13];
    const float* gat_aj    = (const float*)d_in[14];
    const float* gat_ar    = (const float*)d_in[15];
    const float* g2e_ah    = (const float*)d_in[16];
    const float* g2e_at    = (const float*)d_in[17];
    const float* g2e_ar    = (const float*)d_in[18];
    const int*   ei        = (const int*)d_in[19];   // [2, NE1]
    const int*   rel       = (const int*)d_in[20];
    const int*   ei_all    = (const int*)d_in[21];   // [2, NE2]
    const int*   rel_all   = (const int*)d_in[22];
    const int*   lg_merge  = (const int*)d_in[23];   // [2, LGEN]
    const int*   lg_tri    = (const int*)d_in[24];
    float*       out       = (float*)d_out_v;

    float *p_xw, *p_agg, *p_x, *p_dinv, *p_m1, *p_s1, *p_m2, *p_s2, *p_na, *p_nb;
    float *p_e1, *p_e2, *p_rmerge, *p_rtri, *p_xr, *p_rgate, *p_rm, *p_rs, *p_lt, *p_lp, *p_rcar;
    int* p_deg;
    cudaGetSymbolAddress((void**)&p_xw, g_xw);
    cudaGetSymbolAddress((void**)&p_agg, g_agg);
    cudaGetSymbolAddress((void**)&p_x, g_x);
    cudaGetSymbolAddress((void**)&p_dinv, g_dinv);
    cudaGetSymbolAddress((void**)&p_deg, g_deg);
    cudaGetSymbolAddress((void**)&p_m1, g_m1);
    cudaGetSymbolAddress((void**)&p_s1, g_s1);
    cudaGetSymbolAddress((void**)&p_m2, g_m2);
    cudaGetSymbolAddress((void**)&p_s2, g_s2);
    cudaGetSymbolAddress((void**)&p_na, g_na);
    cudaGetSymbolAddress((void**)&p_nb, g_nb);
    cudaGetSymbolAddress((void**)&p_e1, g_e1);
    cudaGetSymbolAddress((void**)&p_e2, g_e2);
    cudaGetSymbolAddress((void**)&p_rmerge, g_rmerge);
    cudaGetSymbolAddress((void**)&p_rtri, g_rtri);
    cudaGetSymbolAddress((void**)&p_xr, g_xr);
    cudaGetSymbolAddress((void**)&p_rgate, g_rgate);
    cudaGetSymbolAddress((void**)&p_rm, g_rm);
    cudaGetSymbolAddress((void**)&p_rs, g_rs);
    cudaGetSymbolAddress((void**)&p_lt, g_lt);
    cudaGetSymbolAddress((void**)&p_lp, g_lp);
    cudaGetSymbolAddress((void**)&p_rcar, g_rcar);

    cudaFuncSetAttribute(k_gemm, cudaFuncAttributeMaxDynamicSharedMemorySize, 160 * 1024);

    const size_t bigBytes = (size_t)NN * EHID * sizeof(float);
    const size_t smemN = 2 * 64 * EHID * sizeof(float);   // 153.6 KB
    const size_t smemR = 2 * 64 * RHD * sizeof(float);    // 51.2 KB
    dim3 gBig((NN + 63) / 64, (EHID + 63) / 64);
    dim3 gRel((RRN + 63) / 64, (RHD + 63) / 64);

    // ---- degrees over edge_index_all (i = row 1) ----
    cudaMemsetAsync(p_deg, 0, NN * sizeof(int), 0);
    k_deg<<<TPE(NE2), 256>>>(ei_all + NE2, NE2, p_deg);
    k_dinv<<<TPE(NN), 256>>>(p_deg, p_dinv, NN);

    // ---- GCN1 + highway1 ----
    k_gemm<<<gBig, 256, smemN>>>(x_e, gcn1_w, p_xw, NN, EHID, EHID);
    cudaMemsetAsync(p_agg, 0, bigBytes, 0);
    k_gcn_agg<<<WPE(NE2), 256>>>(ei_all, ei_all + NE2, p_dinv, p_xw, p_agg, NE2);
    k_gemm<<<gBig, 256, smemN>>>(x_e, hw1_w, p_xw, NN, EHID, EHID);
    k_highway_big<<<TPE(NN * EHID), 256>>>(p_xw, hw1_b, x_e, p_agg, p_x, (float*)0);

    // ---- GCN2 + highway2 (also writes d_out[:,0:300]) ----
    k_gemm<<<gBig, 256, smemN>>>(p_x, gcn2_w, p_xw, NN, EHID, EHID);
    cudaMemsetAsync(p_agg, 0, bigBytes, 0);
    k_gcn_agg<<<WPE(NE2), 256>>>(ei_all, ei_all + NE2, p_dinv, p_xw, p_agg, NE2);
    k_gemm<<<gBig, 256, smemN>>>(p_x, hw2_w, p_xw, NN, EHID, EHID);
    k_highway_big<<<TPE(NN * EHID), 256>>>(p_xw, hw2_b, p_x, p_agg, p_x, out);

    // ---- relation l_gat (merge) ----
    {
        float *mi = p_rm, *mj = p_rm + RRN, *m3 = p_rm + 2 * RRN;
        float *si = p_rs, *sj = p_rs + RRN, *s3 = p_rs + 2 * RRN;
        k_fill_ms<<<TPE(3 * RRN), 256>>>(p_rm, p_rs, 3 * RRN);
        cudaMemsetAsync(p_rmerge, 0, RRN * RHD * sizeof(float), 0);
        k_lgat_p1<<<TPE(LGEN), 256>>>(lg_merge, lg_merge + LGEN, merge_val, mi, mj, LGEN);
        k_lgat_p2<<<TPE(LGEN), 256>>>(lg_merge, lg_merge + LGEN, merge_val, mi, mj, si, sj, LGEN);
        k_lgat_p3<<<TPE(LGEN), 256>>>(lg_merge, lg_merge + LGEN, merge_val, mi, si, mj, sj, m3, p_lt, LGEN);
        k_lgat_p4<<<TPE(LGEN), 256>>>(lg_merge, p_lt, m3, s3, p_lp, LGEN);
        k_lgat_p5<<<WPE(LGEN), 256>>>(lg_merge, lg_merge + LGEN, p_lp, s3, rel_out1, p_rmerge, LGEN);
        k_relu<<<TPE(RRN * RHD), 256>>>(p_rmerge, RRN * RHD);
    }
    // ---- relation l_gat (triangular) ----
    {
        float *mi = p_rm, *mj = p_rm + RRN, *m3 = p_rm + 2 * RRN;
        float *si = p_rs, *sj = p_rs + RRN, *s3 = p_rs + 2 * RRN;
        k_fill_ms<<<TPE(3 * RRN), 256>>>(p_rm, p_rs, 3 * RRN);
        cudaMemsetAsync(p_rtri, 0, RRN * RHD * sizeof(float), 0);
        k_lgat_p1<<<TPE(LGEN), 256>>>(lg_tri, lg_tri + LGEN, tri_val, mi, mj, LGEN);
        k_lgat_p2<<<TPE(LGEN), 256>>>(lg_tri, lg_tri + LGEN, tri_val, mi, mj, si, sj, LGEN);
        k_lgat_p3<<<TPE(LGEN), 256>>>(lg_tri, lg_tri + LGEN, tri_val, mi, si, mj, sj, m3, p_lt, LGEN);
        k_lgat_p4<<<TPE(LGEN), 256>>>(lg_tri, p_lt, m3, s3, p_lp, LGEN);
        k_lgat_p5<<<WPE(LGEN), 256>>>(lg_tri, lg_tri + LGEN, p_lp, s3, rel_tri1, p_rtri, LGEN);
        k_relu<<<TPE(RRN * RHD), 256>>>(p_rtri, RRN * RHD);
    }
    // ---- relation highway + projections ----
    k_gemm<<<gRel, 256, smemR>>>(p_rmerge, hwr_w, p_rgate, RRN, RHD, RHD);
    k_highway_r<<<TPE(RRN * RHD), 256>>>(p_rgate, hwr_b, p_rmerge, p_rtri, p_xr, RRN * RHD, RHD);
    k_rcar<<<WPE(RRN), 256>>>(p_rmerge, p_rtri, gat_ar, p_rcar);

    // ---- GAT over edge_index_all ----
    k_node_dots2<<<WPE(NN), 256>>>(p_x, EHID, EHID, gat_ai, gat_aj, p_na, p_nb, NN);
    k_fill_ms<<<TPE(NN), 256>>>(p_m1, p_s1, NN);
    cudaMemsetAsync(p_agg, 0, bigBytes, 0);
    k_gat_p1<<<TPE(NE2), 256>>>(ei_all, ei_all + NE2, rel_all, p_na, p_nb, p_rcar, p_e1, p_m1, NE2);
    k_seg_exp<<<TPE(NE2), 256>>>(ei_all + NE2, p_e1, p_m1, p_s1, NE2);
    k_gat_p3<<<WPE(NE2), 256>>>(ei_all, ei_all + NE2, p_e1, p_s1, p_x, p_agg, NE2);
    k_concat_gat<<<TPE(NN * EHID), 256>>>(p_agg, out);

    // ---- gat_r_to_e over edge_index ----
    k_node_dots2<<<WPE(NN), 256>>>(out, OUTW, 600, g2e_ah, g2e_at, p_na, p_nb, NN);
    k_dot_rows<<<WPE(RRN), 256>>>(p_xr, RHD, RHD, g2e_ar, p_rcar, RRN);
    k_fill_ms<<<TPE(NN), 256>>>(p_m1, p_s1, NN);
    k_fill_ms<<<TPE(NN), 256>>>(p_m2, p_s2, NN);
    k_g2e_p1<<<TPE(NE1), 256>>>(ei, ei + NE1, rel, p_na, p_nb, p_rcar, p_e1, p_e2, p_m1, p_m2, NE1);
    k_seg_exp<<<TPE(NE1), 256>>>(ei, p_e1, p_m1, p_s1, NE1);
    k_seg_exp<<<TPE(NE1), 256>>>(ei + NE1, p_e2, p_m2, p_s2, NE1);
    k_g2e_p3<<<WPE(NE1), 256>>>(ei, ei + NE1, rel, p_e1, p_s1, p_e2, p_s2, p_xr, out, NE1);
}

// round 2
// speedup vs baseline: 3.2361x; 3.2361x over previous
#include <cuda_runtime.h>
#include <math.h>
#include <stddef.h>
#include <stdint.h>

#define NN    100000
#define EHID  300
#define NE1   400000
#define NE2   800000
#define RRN   2000
#define RHD   100
#define LGEN  60000
#define NEGS  0.01f
#define OUTW  800

// ---------------- device scratch (static allocation; no cudaMalloc) ----------------
static __device__ float g_xw [(size_t)NN * EHID];
static __device__ float g_agg[(size_t)NN * EHID];
static __device__ float g_x  [(size_t)NN * EHID];
static __device__ float g_dinv[NN];
static __device__ int   g_deg [NN];
static __device__ float g_m1[NN], g_s1[NN], g_m2[NN], g_s2[NN];
static __device__ float g_na[NN], g_nb[NN];
static __device__ float g_e1[NE2];
static __device__ float g_e2[NE1];
static __device__ float g_rmerge[RRN * RHD], g_rtri[RRN * RHD];
static __device__ float g_xr[RRN * RHD], g_rgate[RRN * RHD];
static __device__ float g_rm[3 * RRN], g_rs[3 * RRN];
static __device__ float g_lt[LGEN], g_lp[LGEN];
static __device__ float g_rcar[RRN];

// ---------------- device helpers ----------------
__device__ __forceinline__ void atomicMaxF(float* a, float v) {
    if (v >= 0.f) atomicMax((int*)a, __float_as_int(v));
    else          atomicMin((unsigned int*)a, __float_as_uint(v));
}

__device__ __forceinline__ void redAdd4(float* a, float x, float y, float z, float w) {
    asm volatile("red.global.add.v4.f32 [%0], {%1,%2,%3,%4};"
                 :: "l"(a), "f"(x), "f"(y), "f"(z), "f"(w) : "memory");
}

__device__ __forceinline__ float warpSum(float v) {
    #pragma unroll
    for (int o = 16; o; o >>= 1) v += __shfl_xor_sync(0xffffffffu, v, o);
    return v;
}

__device__ __forceinline__ float lrelu(float v) { return v > 0.f ? v : NEGS * v; }
__device__ __forceinline__ float sigf(float z)  { return 1.f / (1.f + expf(-z)); }

__device__ __forceinline__ uint32_t tf32cvt(float x) {
    uint32_t r;
    asm("cvt.rna.tf32.f32 %0, %1;" : "=r"(r) : "f"(x));
    return r;
}

__device__ __forceinline__ void mma_tf32(float* c, const uint32_t* a, const uint32_t* b) {
    asm volatile("mma.sync.aligned.m16n8k8.row.col.f32.tf32.tf32.f32 "
                 "{%0,%1,%2,%3},{%4,%5,%6,%7},{%8,%9},{%0,%1,%2,%3};"
                 : "+f"(c[0]), "+f"(c[1]), "+f"(c[2]), "+f"(c[3])
                 : "r"(a[0]), "r"(a[1]), "r"(a[2]), "r"(a[3]), "r"(b[0]), "r"(b[1]));
}

// ---------------- Tensor-core GEMM (3xTF32): Out[M,OC] = A[M,K] @ W[OC,K]^T ----------------
// BM=128, BN=64, BK=16, 256 threads, warps 4(m)x2(n), each warp 32x32 (2 msub x 4 nsub).
#define GBM 128
#define GBN 64
#define GBK 16
#define SAS 20   // smem row stride in floats (16B-aligned float4 slots, conflict-free)

__global__ __launch_bounds__(256, 2)
void k_gemm_tf32(const float* __restrict__ A, const float* __restrict__ W,
                 float* __restrict__ Out, int M, int K, int OC) {
    __shared__ uint32_t Ah[GBM * SAS], Al[GBM * SAS], Bh[GBN * SAS], Bl[GBN * SAS];
    const int m0 = blockIdx.x * GBM, n0 = blockIdx.y * GBN;
    const int tid = threadIdx.x;
    const int lane = tid & 31, wid = tid >> 5;
    const int wm = wid & 3, wn = wid >> 2;
    const int gid = lane >> 2, tig = lane & 3;
    const int nch = (K + GBK - 1) / GBK;

    float acc[2][4][4];
    #pragma unroll
    for (int s = 0; s < 2; s++)
        #pragma unroll
        for (int t = 0; t < 4; t++)
            #pragma unroll
            for (int q = 0; q < 4; q++) acc[s][t][q] = 0.f;

    // loader coordinates: A has 512 float4 per chunk (2 per thread), B has 256 (1 per thread)
    const int a0r = tid >> 2,         a0c = (tid & 3) * 4;
    const int a1r = (tid + 256) >> 2, a1c = a0c;
    const int br  = tid >> 2,         bc  = a0c;

    float4 pa0, pa1, pb;
    {   // prefetch chunk 0
        int k0 = 0;
        pa0 = make_float4(0.f, 0.f, 0.f, 0.f);
        pa1 = pa0; pb = pa0;
        if (m0 + a0r < M && k0 + a0c < K) pa0 = *(const float4*)&A[(size_t)(m0 + a0r) * K + k0 + a0c];
        if (m0 + a1r < M && k0 + a1c < K) pa1 = *(const float4*)&A[(size_t)(m0 + a1r) * K + k0 + a1c];
        if (n0 + br  < OC && k0 + bc < K) pb  = *(const float4*)&W[(size_t)(n0 + br) * K + k0 + bc];
    }

    for (int kt = 0; kt < nch; kt++) {
        __syncthreads();
        {   // convert + store to smem (hi/lo split)
            uint32_t hx = tf32cvt(pa0.x), hy = tf32cvt(pa0.y), hz = tf32cvt(pa0.z), hw = tf32cvt(pa0.w);
            uint4 h = make_uint4(hx, hy, hz, hw);
            uint4 l = make_uint4(tf32cvt(pa0.x - __uint_as_float(hx)), tf32cvt(pa0.y - __uint_as_float(hy)),
                                 tf32cvt(pa0.z - __uint_as_float(hz)), tf32cvt(pa0.w - __uint_as_float(hw)));
            *(uint4*)&Ah[a0r * SAS + a0c] = h;
            *(uint4*)&Al[a0r * SAS + a0c] = l;

            hx = tf32cvt(pa1.x); hy = tf32cvt(pa1.y); hz = tf32cvt(pa1.z); hw = tf32cvt(pa1.w);
            h = make_uint4(hx, hy, hz, hw);
            l = make_uint4(tf32cvt(pa1.x - __uint_as_float(hx)), tf32cvt(pa1.y - __uint_as_float(hy)),
                           tf32cvt(pa1.z - __uint_as_float(hz)), tf32cvt(pa1.w - __uint_as_float(hw)));
            *(uint4*)&Ah[a1r * SAS + a1c] = h;
            *(uint4*)&Al[a1r * SAS + a1c] = l;

            hx = tf32cvt(pb.x); hy = tf32cvt(pb.y); hz = tf32cvt(pb.z); hw = tf32cvt(pb.w);
            h = make_uint4(hx, hy, hz, hw);
            l = make_uint4(tf32cvt(pb.x - __uint_as_float(hx)), tf32cvt(pb.y - __uint_as_float(hy)),
                           tf32cvt(pb.z - __uint_as_float(hz)), tf32cvt(pb.w - __uint_as_float(hw)));
            *(uint4*)&Bh[br * SAS + bc] = h;
            *(uint4*)&Bl[br * SAS + bc] = l;
        }
        __syncthreads();

        if (kt + 1 < nch) {   // prefetch next chunk (hidden behind mma)
            int k0 = (kt + 1) * GBK;
            pa0 = make_float4(0.f, 0.f, 0.f, 0.f);
            pa1 = pa0; pb = pa0;
            if (m0 + a0r < M && k0 + a0c < K) pa0 = *(const float4*)&A[(size_t)(m0 + a0r) * K + k0 + a0c];
            if (m0 + a1r < M && k0 + a1c < K) pa1 = *(const float4*)&A[(size_t)(m0 + a1r) * K + k0 + a1c];
            if (n0 + br  < OC && k0 + bc < K) pb  = *(const float4*)&W[(size_t)(n0 + br) * K + k0 + bc];
        }

        #pragma unroll
        for (int h8 = 0; h8 < 2; h8++) {
            const int kc = h8 * 8 + tig;
            uint32_t ah[2][4], al[2][4];
            #pragma unroll
            for (int s = 0; s < 2; s++) {
                int r0 = wm * 32 + s * 16 + gid;
                ah[s][0] = Ah[r0 * SAS + kc];       ah[s][1] = Ah[(r0 + 8) * SAS + kc];
                ah[s][2] = Ah[r0 * SAS + kc + 4];   ah[s][3] = Ah[(r0 + 8) * SAS + kc + 4];
                al[s][0] = Al[r0 * SAS + kc];       al[s][1] = Al[(r0 + 8) * SAS + kc];
                al[s][2] = Al[r0 * SAS + kc + 4];   al[s][3] = Al[(r0 + 8) * SAS + kc + 4];
            }
            #pragma unroll
            for (int t = 0; t < 4; t++) {
                int n = wn * 32 + t * 8 + gid;
                uint32_t bhf[2] = { Bh[n * SAS + kc], Bh[n * SAS + kc + 4] };
                uint32_t blf[2] = { Bl[n * SAS + kc], Bl[n * SAS + kc + 4] };
                #pragma unroll
                for (int s = 0; s < 2; s++) {
                    mma_tf32(acc[s][t], ah[s], bhf);
                    mma_tf32(acc[s][t], al[s], bhf);
                    mma_tf32(acc[s][t], ah[s], blf);
                }
            }
        }
    }

    // epilogue
    #pragma unroll
    for (int s = 0; s < 2; s++) {
        #pragma unroll
        for (int t = 0; t < 4; t++) {
            int row = m0 + wm * 32 + s * 16 + gid;
            int col = n0 + wn * 32 + t * 8 + 2 * tig;
            if (col < OC) {
                if (row < M)
                    *(float2*)&Out[(size_t)row * OC + col] = make_float2(acc[s][t][0], acc[s][t][1]);
                if (row + 8 < M)
                    *(float2*)&Out[(size_t)(row + 8) * OC + col] = make_float2(acc[s][t][2], acc[s][t][3]);
            }
        }
    }
}

// ---------------- scalar GEMM (kept for the tiny relation highway gate) ----------------
__global__ void k_gemm(const float* __restrict__ A, const float* __restrict__ W,
                       float* __restrict__ Out, int M, int K, int OC) {
    extern __shared__ float sm[];
    float* As = sm;
    float* Ws = sm + 64 * K;
    const int n0 = blockIdx.x * 64, o0 = blockIdx.y * 64;
    const int tid = threadIdx.x;
    const int Kv4 = K >> 2;

    for (int idx = tid; idx < 64 * Kv4; idx += 256) {
        int r = idx / Kv4, k4 = idx - r * Kv4;
        float4 v = make_float4(0.f, 0.f, 0.f, 0.f);
        if (n0 + r < M) v = *(const float4*)&A[(size_t)(n0 + r) * K + k4 * 4];
        *(float4*)&As[r * K + k4 * 4] = v;
    }
    for (int idx = tid; idx < 64 * Kv4; idx += 256) {
        int r = idx / Kv4, k4 = idx - r * Kv4;
        float4 v = make_float4(0.f, 0.f, 0.f, 0.f);
        if (o0 + r < OC) v = *(const float4*)&W[(size_t)(o0 + r) * K + k4 * 4];
        *(float4*)&Ws[r * K + k4 * 4] = v;
    }
    __syncthreads();

    const int tx = tid & 15, ty = tid >> 4;
    const float* Ap = &As[(ty * 4) * K];
    const float* Wp = &Ws[(tx * 4) * K];
    float acc[4][4] = {};
    #pragma unroll 4
    for (int k = 0; k < K; k++) {
        float a0 = Ap[k], a1 = Ap[K + k], a2 = Ap[2 * K + k], a3 = Ap[3 * K + k];
        float w0 = Wp[k], w1 = Wp[K + k], w2 = Wp[2 * K + k], w3 = Wp[3 * K + k];
        acc[0][0] += a0 * w0; acc[0][1] += a0 * w1; acc[0][2] += a0 * w2; acc[0][3] += a0 * w3;
        acc[1][0] += a1 * w0; acc[1][1] += a1 * w1; acc[1][2] += a1 * w2; acc[1][3] += a1 * w3;
        acc[2][0] += a2 * w0; acc[2][1] += a2 * w1; acc[2][2] += a2 * w2; acc[2][3] += a2 * w3;
        acc[3][0] += a3 * w0; acc[3][1] += a3 * w1; acc[3][2] += a3 * w2; acc[3][3] += a3 * w3;
    }
    #pragma unroll
    for (int q = 0; q < 4; q++) {
        int row = n0 + ty * 4 + q;
        if (row >= M) continue;
        #pragma unroll
        for (int p = 0; p < 4; p++) {
            int col = o0 + tx * 4 + p;
            if (col < OC) Out[(size_t)row * OC + col] = acc[q][p];
        }
    }
}

// ---------------- small utility kernels ----------------
__global__ void k_fill_ms(float* m, float* s, int n) {
    int i = blockIdx.x * 256 + threadIdx.x;
    if (i < n) { m[i] = __int_as_float(0xff800000); s[i] = 0.f; }
}
__global__ void k_relu(float* p, int n) {
    int i = blockIdx.x * 256 + threadIdx.x;
    if (i < n) p[i] = fmaxf(p[i], 0.f);
}
__global__ void k_deg(const int* __restrict__ ei, int nE, int* __restrict__ deg) {
    int e = blockIdx.x * 256 + threadIdx.x;
    if (e < nE) atomicAdd(&deg[ei[e]], 1);
}
__global__ void k_dinv(const int* __restrict__ deg, float* __restrict__ dinv, int n) {
    int i = blockIdx.x * 256 + threadIdx.x;
    if (i < n) { int d = deg[i]; dinv[i] = d > 0 ? rsqrtf((float)d) : 0.f; }
}

// ---------------- GCN edge aggregation ----------------
__global__ void k_gcn_agg(const int* __restrict__ ej, const int* __restrict__ ei,
                          const float* __restrict__ dinv, const float* __restrict__ xw,
                          float* __restrict__ agg, int nE) {
    int w = (blockIdx.x * blockDim.x + threadIdx.x) >> 5;
    int lane = threadIdx.x & 31;
    if (w >= nE) return;
    int j = ej[w], i = ei[w];
    float norm = dinv[j] * dinv[i];
    const float4* src = (const float4*)&xw[(size_t)j * EHID];
    float* dst = &agg[(size_t)i * EHID];
    for (int c4 = lane; c4 < EHID / 4; c4 += 32) {
        float4 v = src[c4];
        redAdd4(dst + c4 * 4, norm * v.x, norm * v.y, norm * v.z, norm * v.w);
    }
}

// ---------------- highway kernels ----------------
__global__ void k_highway_big(const float* __restrict__ gate, const float* __restrict__ bias,
                              const float* __restrict__ x1, const float* __restrict__ agg,
                              float* __restrict__ xout, float* __restrict__ dout) {
    int idx = blockIdx.x * 256 + threadIdx.x;
    if (idx >= NN * EHID) return;
    int c = idx % EHID;
    float g = sigf(gate[idx] + bias[c]);
    float a = fmaxf(agg[idx], 0.f);
    float v = g * a + (1.f - g) * x1[idx];
    xout[idx] = v;
    if (dout) { int n = idx / EHID; dout[(size_t)n * OUTW + c] = v; }
}

__global__ void k_highway_r(const float* __restrict__ gate, const float* __restrict__ bias,
                            const float* __restrict__ x1, const float* __restrict__ x2,
                            float* __restrict__ out, int n, int C) {
    int idx = blockIdx.x * 256 + threadIdx.x;
    if (idx >= n * C) return;
    int c = idx % C;
    float g = sigf(gate[idx] + bias[c]);
    out[idx] = g * x2[idx] + (1.f - g) * x1[idx];
}

// ---------------- l_gat passes ----------------
__global__ void k_lgat_p1(const int* __restrict__ ej, const int* __restrict__ ei,
                          const float* __restrict__ val, float* mi, float* mj, int nE) {
    int e = blockIdx.x * 256 + threadIdx.x;
    if (e >= nE) return;
    float v = val[e];
    atomicMaxF(&mi[ei[e]], v);
    atomicMaxF(&mj[ej[e]], v);
}
__global__ void k_lgat_p2(const int* __restrict__ ej, const int* __restrict__ ei,
                          const float* __restrict__ val, const float* __restrict__ mi,
                          const float* __restrict__ mj, float* si, float* sj, int nE) {
    int e = blockIdx.x * 256 + threadIdx.x;
    if (e >= nE) return;
    float v = val[e];
    atomicAdd(&si[ei[e]], expf(v - mi[ei[e]]));
    atomicAdd(&sj[ej[e]], expf(v - mj[ej[e]]));
}
__global__ void k_lgat_p3(const int* __restrict__ ej, const int* __restrict__ ei,
                          const float* __restrict__ val,
                          const float* __restrict__ mi, const float* __restrict__ si,
                          const float* __restrict__ mj, const float* __restrict__ sj,
                          float* m3, float* tbuf, int nE) {
    int e = blockIdx.x * 256 + threadIdx.x;
    if (e >= nE) return;
    int i = ei[e], j = ej[e];
    float v = val[e];
    float vi = expf(v - mi[i]) / (si[i] + 1e-16f);
    float vj = expf(v - mj[j]) / (sj[j] + 1e-16f);
    float t = vi + vj;
    tbuf[e] = t;
    atomicMaxF(&m3[j], t);
}
__global__ void k_lgat_p4(const int* __restrict__ ej, const float* __restrict__ tbuf,
                          const float* __restrict__ m3, float* s3, float* pbuf, int nE) {
    int e = blockIdx.x * 256 + threadIdx.x;
    if (e >= nE) return;
    float p = expf(tbuf[e] - m3[ej[e]]);
    pbuf[e] = p;
    atomicAdd(&s3[ej[e]], p);
}
__global__ void k_lgat_p5(const int* __restrict__ ej, const int* __restrict__ ei,
                          const float* __restrict__ pbuf, const float* __restrict__ s3,
                          const float* __restrict__ x, float* __restrict__ outb, int nE) {
    int w = (blockIdx.x * blockDim.x + threadIdx.x) >> 5;
    int lane = threadIdx.x & 31;
    if (w >= nE) return;
    int j = ej[w], i = ei[w];
    float alpha = pbuf[w] / (s3[j] + 1e-16f);
    if (lane < RHD / 4) {
        float4 v = ((const float4*)&x[(size_t)j * RHD])[lane];
        redAdd4(&outb[(size_t)i * RHD + lane * 4], alpha * v.x, alpha * v.y, alpha * v.z, alpha * v.w);
    }
}

// ---------------- per-node / per-row dot products ----------------
__global__ void k_node_dots2(const float* __restrict__ X, int stride, int len,
                             const float* __restrict__ va, const float* __restrict__ vb,
                             float* __restrict__ oa, float* __restrict__ ob, int n) {
    int w = (blockIdx.x * blockDim.x + threadIdx.x) >> 5;
    int lane = threadIdx.x & 31;
    if (w >= n) return;
    const float* row = X + (size_t)w * stride;
    float sa = 0.f, sb = 0.f;
    for (int c = lane; c < len; c += 32) { float x = row[c]; sa += x * va[c]; sb += x * vb[c]; }
    sa = warpSum(sa); sb = warpSum(sb);
    if (lane == 0) { oa[w] = sa; ob[w] = sb; }
}
__global__ void k_dot_rows(const float* __restrict__ X, int stride, int len,
                           const float* __restrict__ v, float* __restrict__ out, int n) {
    int w = (blockIdx.x * blockDim.x + threadIdx.x) >> 5;
    int lane = threadIdx.x & 31;
    if (w >= n) return;
    const float* row = X + (size_t)w * stride;
    float s = 0.f;
    for (int c = lane; c < len; c += 32) s += row[c] * v[c];
    s = warpSum(s);
    if (lane == 0) out[w] = s;
}
__global__ void k_rcar(const float* __restrict__ mrg, const float* __restrict__ tri,
                       const float* __restrict__ ar, float* __restrict__ rcar) {
    int w = (blockIdx.x * blockDim.x + threadIdx.x) >> 5;
    int lane = threadIdx.x & 31;
    if (w >= RRN) return;
    float s = 0.f;
    for (int c = lane; c < RHD; c += 32)
        s += mrg[(size_t)w * RHD + c] * ar[c] + tri[(size_t)w * RHD + c] * ar[RHD + c];
    s = warpSum(s);
    if (lane == 0) rcar[w] = s;
}

// ---------------- GAT over edge_index_all ----------------
__global__ void k_gat_p1(const int* __restrict__ ej, const int* __restrict__ ei,
                         const int* __restrict__ ra, const float* __restrict__ xa,
                         const float* __restrict__ xb, const float* __restrict__ rcar,
                         float* __restrict__ ebuf, float* m, int nE) {
    int e = blockIdx.x * 256 + threadIdx.x;
    if (e >= nE) return;
    int i = ei[e], j = ej[e];
    int rr = ra[e]; if (rr >= RRN) rr -= RRN;
    float v = lrelu(xa[i] + xb[j] + rcar[rr]);
    ebuf[e] = v;
    atomicMaxF(&m[i], v);
}
__global__ void k_seg_exp(const int* __restrict__ idx, float* __restrict__ ebuf,
                          const float* __restrict__ m, float* s, int nE) {
    int e = blockIdx.x * 256 + threadIdx.x;
    if (e >= nE) return;
    int g = idx[e];
    float p = expf(ebuf[e] - m[g]);
    ebuf[e] = p;
    atomicAdd(&s[g], p);
}
__global__ void k_gat_p3(const int* __restrict__ ej, const int* __restrict__ ei,
                         const float* __restrict__ pbuf, const float* __restrict__ s,
                         const float* __restrict__ x, float* __restrict__ agg, int nE) {
    int w = (blockIdx.x * blockDim.x + threadIdx.x) >> 5;
    int lane = threadIdx.x & 31;
    if (w >= nE) return;
    int j = ej[w], i = ei[w];
    float alpha = pbuf[w] / (s[i] + 1e-16f);
    const float4* src = (const float4*)&x[(size_t)j * EHID];
    float* dst = &agg[(size_t)i * EHID];
    for (int c4 = lane; c4 < EHID / 4; c4 += 32) {
        float4 v = src[c4];
        redAdd4(dst + c4 * 4, alpha * v.x, alpha * v.y, alpha * v.z, alpha * v.w);
    }
}
__global__ void k_concat_gat(const float* __restrict__ agg, float* __restrict__ out) {
    int idx = blockIdx.x * 256 + threadIdx.x;
    if (idx >= NN * EHID) return;
    int n = idx / EHID, c = idx - n * EHID;
    out[(size_t)n * OUTW + 300 + c] = fmaxf(agg[idx], 0.f);
    if (c < 200) out[(size_t)n * OUTW + 600 + c] = 0.f;
}

// ---------------- gat_r_to_e ----------------
__global__ void k_g2e_p1(const int* __restrict__ eh, const int* __restrict__ et,
                         const int* __restrict__ rel, const float* __restrict__ xh,
                         const float* __restrict__ xt, const float* __restrict__ er,
                         float* __restrict__ e1, float* __restrict__ e2,
                         float* m1, float* m2, int nE) {
    int e = blockIdx.x * 256 + threadIdx.x;
    if (e >= nE) return;
    int h = eh[e], t = et[e], r = rel[e];
    float w = er[r];
    float a = lrelu(xh[h] + w);
    float b = lrelu(xt[t] + w);
    e1[e] = a; e2[e] = b;
    atomicMaxF(&m1[h], a);
    atomicMaxF(&m2[t], b);
}
__global__ void k_g2e_p3(const int* __restrict__ eh, const int* __restrict__ et,
                         const int* __restrict__ rel,
                         const float* __restrict__ p1, const float* __restrict__ s1,
                         const float* __restrict__ p2, const float* __restrict__ s2,
                         const float* __restrict__ xr, float* __restrict__ out, int nE) {
    int w = (blockIdx.x * blockDim.x + threadIdx.x) >> 5;
    int lane = threadIdx.x & 31;
    if (w >= nE) return;
    int h = eh[w], t = et[w], r = rel[w];
    float a1 = p1[w] / (s1[h] + 1e-16f);
    float a2 = p2[w] / (s2[t] + 1e-16f);
    if (lane < RHD / 4) {
        float4 v = ((const float4*)&xr[(size_t)r * RHD])[lane];
        redAdd4(&out[(size_t)h * OUTW + 600 + lane * 4], a1 * v.x, a1 * v.y, a1 * v.z, a1 * v.w);
        redAdd4(&out[(size_t)t * OUTW + 700 + lane * 4], a2 * v.x, a2 * v.y, a2 * v.z, a2 * v.w);
    }
}

// ---------------- host ----------------
static inline int TPE(int n) { return (n + 255) / 256; }
static inline int WPE(int n) { return (n + 7) / 8; }

extern "C" void kernel_launch(void* const* d_in, const int* in_sizes, int n_in,
                              void* d_out_v, int out_size) {
    const float* x_e       = (const float*)d_in[0];
    const float* merge_val = (const float*)d_in[1];
    const float* tri_val   = (const float*)d_in[2];
    const float* gcn1_w    = (const float*)d_in[3];
    const float* hw1_w     = (const float*)d_in[4];
    const float* hw1_b     = (const float*)d_in[5];
    const float* gcn2_w    = (const float*)d_in[6];
    const float* hw2_w     = (const float*)d_in[7];
    const float* hw2_b     = (const float*)d_in[8];
    const float* rel_out1  = (const float*)d_in[9];
    const float* rel_tri1  = (const float*)d_in[10];
    const float* hwr_w     = (const float*)d_in[11];
    const float* hwr_b     = (const float*)d_in[12];
    const float* gat_ai    = (const float*)d_in[13];
    const float* gat_aj    = (const float*)d_in[14];
    const float* gat_ar    = (const float*)d_in[15];
    const float* g2e_ah    = (const float*)d_in[16];
    const float* g2e_at    = (const float*)d_in[17];
    const float* g2e_ar    = (const float*)d_in[18];
    const int*   ei        = (const int*)d_in[19];
    const int*   rel       = (const int*)d_in[20];
    const int*   ei_all    = (const int*)d_in[21];
    const int*   rel_all   = (const int*)d_in[22];
    const int*   lg_merge  = (const int*)d_in[23];
    const int*   lg_tri    = (const int*)d_in[24];
    float*       out       = (float*)d_out_v;

    float *p_xw, *p_agg, *p_x, *p_dinv, *p_m1, *p_s1, *p_m2, *p_s2, *p_na, *p_nb;
    float *p_e1, *p_e2, *p_rmerge, *p_rtri, *p_xr, *p_rgate, *p_rm, *p_rs, *p_lt, *p_lp, *p_rcar;
    int* p_deg;
    cudaGetSymbolAddress((void**)&p_xw, g_xw);
    cudaGetSymbolAddress((void**)&p_agg, g_agg);
    cudaGetSymbolAddress((void**)&p_x, g_x);
    cudaGetSymbolAddress((void**)&p_dinv, g_dinv);
    cudaGetSymbolAddress((void**)&p_deg, g_deg);
    cudaGetSymbolAddress((void**)&p_m1, g_m1);
    cudaGetSymbolAddress((void**)&p_s1, g_s1);
    cudaGetSymbolAddress((void**)&p_m2, g_m2);
    cudaGetSymbolAddress((void**)&p_s2, g_s2);
    cudaGetSymbolAddress((void**)&p_na, g_na);
    cudaGetSymbolAddress((void**)&p_nb, g_nb);
    cudaGetSymbolAddress((void**)&p_e1, g_e1);
    cudaGetSymbolAddress((void**)&p_e2, g_e2);
    cudaGetSymbolAddress((void**)&p_rmerge, g_rmerge);
    cudaGetSymbolAddress((void**)&p_rtri, g_rtri);
    cudaGetSymbolAddress((void**)&p_xr, g_xr);
    cudaGetSymbolAddress((void**)&p_rgate, g_rgate);
    cudaGetSymbolAddress((void**)&p_rm, g_rm);
    cudaGetSymbolAddress((void**)&p_rs, g_rs);
    cudaGetSymbolAddress((void**)&p_lt, g_lt);
    cudaGetSymbolAddress((void**)&p_lp, g_lp);
    cudaGetSymbolAddress((void**)&p_rcar, g_rcar);

    cudaFuncSetAttribute(k_gemm, cudaFuncAttributeMaxDynamicSharedMemorySize, 160 * 1024);

    const size_t bigBytes = (size_t)NN * EHID * sizeof(float);
    const size_t smemR = 2 * 64 * RHD * sizeof(float);
    dim3 gT((NN + GBM - 1) / GBM, (EHID + GBN - 1) / GBN);   // (782, 5)
    dim3 gRel((RRN + 63) / 64, (RHD + 63) / 64);

    // ---- degrees ----
    cudaMemsetAsync(p_deg, 0, NN * sizeof(int), 0);
    k_deg<<<TPE(NE2), 256>>>(ei_all + NE2, NE2, p_deg);
    k_dinv<<<TPE(NN), 256>>>(p_deg, p_dinv, NN);

    // ---- GCN1 + highway1 ----
    k_gemm_tf32<<<gT, 256>>>(x_e, gcn1_w, p_xw, NN, EHID, EHID);
    cudaMemsetAsync(p_agg, 0, bigBytes, 0);
    k_gcn_agg<<<WPE(NE2), 256>>>(ei_all, ei_all + NE2, p_dinv, p_xw, p_agg, NE2);
    k_gemm_tf32<<<gT, 256>>>(x_e, hw1_w, p_xw, NN, EHID, EHID);
    k_highway_big<<<TPE(NN * EHID), 256>>>(p_xw, hw1_b, x_e, p_agg, p_x, (float*)0);

    // ---- GCN2 + highway2 ----
    k_gemm_tf32<<<gT, 256>>>(p_x, gcn2_w, p_xw, NN, EHID, EHID);
    cudaMemsetAsync(p_agg, 0, bigBytes, 0);
    k_gcn_agg<<<WPE(NE2), 256>>>(ei_all, ei_all + NE2, p_dinv, p_xw, p_agg, NE2);
    k_gemm_tf32<<<gT, 256>>>(p_x, hw2_w, p_xw, NN, EHID, EHID);
    k_highway_big<<<TPE(NN * EHID), 256>>>(p_xw, hw2_b, p_x, p_agg, p_x, out);

    // ---- relation l_gat (merge) ----
    {
        float *mi = p_rm, *mj = p_rm + RRN, *m3 = p_rm + 2 * RRN;
        float *si = p_rs, *sj = p_rs + RRN, *s3 = p_rs + 2 * RRN;
        k_fill_ms<<<TPE(3 * RRN), 256>>>(p_rm, p_rs, 3 * RRN);
        cudaMemsetAsync(p_rmerge, 0, RRN * RHD * sizeof(float), 0);
        k_lgat_p1<<<TPE(LGEN), 256>>>(lg_merge, lg_merge + LGEN, merge_val, mi, mj, LGEN);
        k_lgat_p2<<<TPE(LGEN), 256>>>(lg_merge, lg_merge + LGEN, merge_val, mi, mj, si, sj, LGEN);
        k_lgat_p3<<<TPE(LGEN), 256>>>(lg_merge, lg_merge + LGEN, merge_val, mi, si, mj, sj, m3, p_lt, LGEN);
        k_lgat_p4<<<TPE(LGEN), 256>>>(lg_merge, p_lt, m3, s3, p_lp, LGEN);
        k_lgat_p5<<<WPE(LGEN), 256>>>(lg_merge, lg_merge + LGEN, p_lp, s3, rel_out1, p_rmerge, LGEN);
        k_relu<<<TPE(RRN * RHD), 256>>>(p_rmerge, RRN * RHD);
    }
    // ---- relation l_gat (triangular) ----
    {
        float *mi = p_rm, *mj = p_rm + RRN, *m3 = p_rm + 2 * RRN;
        float *si = p_rs, *sj = p_rs + RRN, *s3 = p_rs + 2 * RRN;
        k_fill_ms<<<TPE(3 * RRN), 256>>>(p_rm, p_rs, 3 * RRN);
        cudaMemsetAsync(p_rtri, 0, RRN * RHD * sizeof(float), 0);
        k_lgat_p1<<<TPE(LGEN), 256>>>(lg_tri, lg_tri + LGEN, tri_val, mi, mj, LGEN);
        k_lgat_p2<<<TPE(LGEN), 256>>>(lg_tri, lg_tri + LGEN, tri_val, mi, mj, si, sj, LGEN);
        k_lgat_p3<<<TPE(LGEN), 256>>>(lg_tri, lg_tri + LGEN, tri_val, mi, si, mj, sj, m3, p_lt, LGEN);
        k_lgat_p4<<<TPE(LGEN), 256>>>(lg_tri, p_lt, m3, s3, p_lp, LGEN);
        k_lgat_p5<<<WPE(LGEN), 256>>>(lg_tri, lg_tri + LGEN, p_lp, s3, rel_tri1, p_rtri, LGEN);
        k_relu<<<TPE(RRN * RHD), 256>>>(p_rtri, RRN * RHD);
    }
    // ---- relation highway + projections ----
    k_gemm<<<gRel, 256, smemR>>>(p_rmerge, hwr_w, p_rgate, RRN, RHD, RHD);
    k_highway_r<<<TPE(RRN * RHD), 256>>>(p_rgate, hwr_b, p_rmerge, p_rtri, p_xr, RRN * RHD, RHD);
    k_rcar<<<WPE(RRN), 256>>>(p_rmerge, p_rtri, gat_ar, p_rcar);

    // ---- GAT over edge_index_all ----
    k_node_dots2<<<WPE(NN), 256>>>(p_x, EHID, EHID, gat_ai, gat_aj, p_na, p_nb, NN);
    k_fill_ms<<<TPE(NN), 256>>>(p_m1, p_s1, NN);
    cudaMemsetAsync(p_agg, 0, bigBytes, 0);
    k_gat_p1<<<TPE(NE2), 256>>>(ei_all, ei_all + NE2, rel_all, p_na, p_nb, p_rcar, p_e1, p_m1, NE2);
    k_seg_exp<<<TPE(NE2), 256>>>(ei_all + NE2, p_e1, p_m1, p_s1, NE2);
    k_gat_p3<<<WPE(NE2), 256>>>(ei_all, ei_all + NE2, p_e1, p_s1, p_x, p_agg, NE2);
    k_concat_gat<<<TPE(NN * EHID), 256>>>(p_agg, out);

    // ---- gat_r_to_e ----
    k_node_dots2<<<WPE(NN), 256>>>(out, OUTW, 600, g2e_ah, g2e_at, p_na, p_nb, NN);
    k_dot_rows<<<WPE(RRN), 256>>>(p_xr, RHD, RHD, g2e_ar, p_rcar, RRN);
    k_fill_ms<<<TPE(NN), 256>>>(p_m1, p_s1, NN);
    k_fill_ms<<<TPE(NN), 256>>>(p_m2, p_s2, NN);
    k_g2e_p1<<<TPE(NE1), 256>>>(ei, ei + NE1, rel, p_na, p_nb, p_rcar, p_e1, p_e2, p_m1, p_m2, NE1);
    k_seg_exp<<<TPE(NE1), 256>>>(ei, p_e1, p_m1, p_s1, NE1);
    k_seg_exp<<<TPE(NE1), 256>>>(ei + NE1, p_e2, p_m2, p_s2, NE1);
    k_g2e_p3<<<WPE(NE1), 256>>>(ei, ei + NE1, rel, p_e1, p_s1, p_e2, p_s2, p_xr, out, NE1);
}

// round 6
// speedup vs baseline: 4.2096x; 1.3008x over previous
#include <cuda_runtime.h>
#include <cuda_bf16.h>
#include <math.h>
#include <stddef.h>
#include <stdint.h>

#define NN    100000
#define EHID  300
#define NE1   400000
#define NE2   800000
#define RRN   2000
#define RHD   100
#define LGEN  60000
#define NEGS  0.01f
#define OUTW  800

// ---------------- device scratch ----------------
static __device__ float g_xw [(size_t)NN * EHID];
static __device__ float g_agg[(size_t)NN * EHID];
static __device__ float g_x  [(size_t)NN * EHID];
static __device__ float g_dinv[NN];
static __device__ int   g_deg [NN];
static __device__ float g_m1[NN], g_s1[NN], g_m2[NN], g_s2[NN];
static __device__ float g_na[NN], g_nb[NN];
static __device__ float g_e1[NE2];
static __device__ float g_e2[NE1];
static __device__ float g_rmerge[RRN * RHD], g_rtri[RRN * RHD];
static __device__ float g_xr[RRN * RHD], g_rgate[RRN * RHD];
static __device__ float g_rm[3 * RRN], g_rs[3 * RRN];
static __device__ float g_lt[LGEN], g_lp[LGEN];
static __device__ float g_rcar[RRN];

// ---------------- generic device helpers ----------------
__device__ __forceinline__ void atomicMaxF(float* a, float v) {
    if (v >= 0.f) atomicMax((int*)a, __float_as_int(v));
    else          atomicMin((unsigned int*)a, __float_as_uint(v));
}
__device__ __forceinline__ void redAdd4(float* a, float x, float y, float z, float w) {
    asm volatile("red.global.add.v4.f32 [%0], {%1,%2,%3,%4};"
                 :: "l"(a), "f"(x), "f"(y), "f"(z), "f"(w) : "memory");
}
__device__ __forceinline__ float warpSum(float v) {
    #pragma unroll
    for (int o = 16; o; o >>= 1) v += __shfl_xor_sync(0xffffffffu, v, o);
    return v;
}
__device__ __forceinline__ float lrelu(float v) { return v > 0.f ? v : NEGS * v; }
__device__ __forceinline__ float sigf(float z)  { return 1.f / (1.f + expf(-z)); }

__device__ __forceinline__ uint32_t smem_u32(const void* p) {
    uint32_t a;
    asm("{ .reg .u64 t; cvta.to.shared.u64 t, %1; cvt.u32.u64 %0, t; }" : "=r"(a) : "l"(p));
    return a;
}
__device__ __forceinline__ void ldsm4(uint32_t* r, uint32_t addr) {
    asm volatile("ldmatrix.sync.aligned.m8n8.x4.shared.b16 {%0,%1,%2,%3}, [%4];"
                 : "=r"(r[0]), "=r"(r[1]), "=r"(r[2]), "=r"(r[3]) : "r"(addr));
}
__device__ __forceinline__ void mma_bf16(float* c, const uint32_t* a, const uint32_t* b) {
    asm volatile("mma.sync.aligned.m16n8k16.row.col.f32.bf16.bf16.f32 "
                 "{%0,%1,%2,%3},{%4,%5,%6,%7},{%8,%9},{%0,%1,%2,%3};"
                 : "+f"(c[0]), "+f"(c[1]), "+f"(c[2]), "+f"(c[3])
                 : "r"(a[0]), "r"(a[1]), "r"(a[2]), "r"(a[3]), "r"(b[0]), "r"(b[1]));
}

// ---------------- bf16 hi/lo 3-pass GEMM: Out[M,OC] = A[M,K] @ W[OC,K]^T ----------------
// BM=128, BN=64, BK=32; 256 threads, warps 4(m)x2(n); warp tile 32x32 (2 msub x 4 nsub).
// smem rows stride 40 bf16 (80B) -> conflict-free ldmatrix. Double-buffered.
#define BBM 128
#define BBN 64
#define BBK 32
#define BST 40                       // bf16 elements per smem row
#define SZ_A (BBM * BST * 2)         // 10240 B (one piece)
#define SZ_W (BBN * BST * 2)         // 5120 B
#define BUFB (2 * SZ_A + 2 * SZ_W)   // 30720 B per buffer
#define SMEM_GB (2 * BUFB)           // 61440 B

__device__ __forceinline__ void cvt_hilo(float4 v, uint2& h, uint2& l) {
    __nv_bfloat16 h0 = __float2bfloat16(v.x), h1 = __float2bfloat16(v.y);
    __nv_bfloat16 h2 = __float2bfloat16(v.z), h3 = __float2bfloat16(v.w);
    __nv_bfloat16 l0 = __float2bfloat16(v.x - __bfloat162float(h0));
    __nv_bfloat16 l1 = __float2bfloat16(v.y - __bfloat162float(h1));
    __nv_bfloat16 l2 = __float2bfloat16(v.z - __bfloat162float(h2));
    __nv_bfloat16 l3 = __float2bfloat16(v.w - __bfloat162float(h3));
    __nv_bfloat162 ha = __halves2bfloat162(h0, h1), hb = __halves2bfloat162(h2, h3);
    __nv_bfloat162 la = __halves2bfloat162(l0, l1), lb = __halves2bfloat162(l2, l3);
    h = make_uint2(*(uint32_t*)&ha, *(uint32_t*)&hb);
    l = make_uint2(*(uint32_t*)&la, *(uint32_t*)&lb);
}

__global__ __launch_bounds__(256, 2)
void k_gemm_bf16(const float* __restrict__ A, const float* __restrict__ W,
                 float* __restrict__ Out, int M, int K, int OC) {
    extern __shared__ char smem[];
    const int tid = threadIdx.x, lane = tid & 31, wid = tid >> 5;
    const int wm = wid & 3, wn = wid >> 2;
    const int m0 = blockIdx.x * BBM, n0 = blockIdx.y * BBN;
    const int nch = (K + BBK - 1) / BBK;

    const uint32_t sbase = smem_u32(smem);

    float acc[2][4][4];
    #pragma unroll
    for (int s = 0; s < 2; s++)
        #pragma unroll
        for (int n = 0; n < 4; n++)
            #pragma unroll
            for (int q = 0; q < 4; q++) acc[s][n][q] = 0.f;

    // loader coords: A 1024 float4/chunk (4/thread), W 512 (2/thread)
    float4 pa[4], pw[2];
    {
        int k0 = 0;
        #pragma unroll
        for (int q = 0; q < 4; q++) {
            int idx = q * 256 + tid, r = idx >> 3, c4 = (idx & 7) * 4;
            pa[q] = make_float4(0.f, 0.f, 0.f, 0.f);
            if (m0 + r < M && k0 + c4 < K) pa[q] = *(const float4*)&A[(size_t)(m0 + r) * K + k0 + c4];
        }
        #pragma unroll
        for (int q = 0; q < 2; q++) {
            int idx = q * 256 + tid, r = idx >> 3, c4 = (idx & 7) * 4;
            pw[q] = make_float4(0.f, 0.f, 0.f, 0.f);
            if (n0 + r < OC && k0 + c4 < K) pw[q] = *(const float4*)&W[(size_t)(n0 + r) * K + k0 + c4];
        }
    }

    // ldmatrix lane-address components
    const int lrow = lane & 7, lsel = lane >> 3;
    const int aRowB = wm * 32 + ((lsel & 1) << 3) + lrow;
    const int aColB = (lsel >> 1) << 3;
    const int bRowB = wn * 32 + ((lsel >> 1) << 3) + lrow;
    const int bColB = (lsel & 1) << 3;

    int buf = 0;
    for (int kt = 0; kt < nch; kt++) {
        char* sb = smem + buf * BUFB;
        char* sAh = sb;
        char* sAl = sb + SZ_A;
        char* sWh = sb + 2 * SZ_A;
        char* sWl = sb + 2 * SZ_A + SZ_W;

        // convert + store prefetched regs
        #pragma unroll
        for (int q = 0; q < 4; q++) {
            int idx = q * 256 + tid, r = idx >> 3, c4 = (idx & 7) * 4;
            uint2 h, l; cvt_hilo(pa[q], h, l);
            *(uint2*)(sAh + (r * BST + c4) * 2) = h;
            *(uint2*)(sAl + (r * BST + c4) * 2) = l;
        }
        #pragma unroll
        for (int q = 0; q < 2; q++) {
            int idx = q * 256 + tid, r = idx >> 3, c4 = (idx & 7) * 4;
            uint2 h, l; cvt_hilo(pw[q], h, l);
            *(uint2*)(sWh + (r * BST + c4) * 2) = h;
            *(uint2*)(sWl + (r * BST + c4) * 2) = l;
        }
        __syncthreads();

        if (kt + 1 < nch) {   // prefetch next chunk
            int k0 = (kt + 1) * BBK;
            #pragma unroll
            for (int q = 0; q < 4; q++) {
                int idx = q * 256 + tid, r = idx >> 3, c4 = (idx & 7) * 4;
                pa[q] = make_float4(0.f, 0.f, 0.f, 0.f);
                if (m0 + r < M && k0 + c4 < K) pa[q] = *(const float4*)&A[(size_t)(m0 + r) * K + k0 + c4];
            }
            #pragma unroll
            for (int q = 0; q < 2; q++) {
                int idx = q * 256 + tid, r = idx >> 3, c4 = (idx & 7) * 4;
                pw[q] = make_float4(0.f, 0.f, 0.f, 0.f);
                if (n0 + r < OC && k0 + c4 < K) pw[q] = *(const float4*)&W[(size_t)(n0 + r) * K + k0 + c4];
            }
        }

        const uint32_t uAh = sbase + buf * BUFB;
        const uint32_t uAl = uAh + SZ_A;
        const uint32_t uWh = uAh + 2 * SZ_A;
        const uint32_t uWl = uWh + SZ_W;

        #pragma unroll
        for (int h = 0; h < 2; h++) {
            uint32_t ah[2][4], al[2][4], bh[2][4], bl[2][4];
            #pragma unroll
            for (int s = 0; s < 2; s++) {
                uint32_t off = ((aRowB + s * 16) * BST + h * 16 + aColB) * 2;
                ldsm4(ah[s], uAh + off);
                ldsm4(al[s], uAl + off);
            }
            #pragma unroll
            for (int p = 0; p < 2; p++) {
                uint32_t off = ((bRowB + p * 16) * BST + h * 16 + bColB) * 2;
                ldsm4(bh[p], uWh + off);
                ldsm4(bl[p], uWl + off);
            }
            #pragma unroll
            for (int s = 0; s < 2; s++) {
                #pragma unroll
                for (int n = 0; n < 4; n++) {
                    const uint32_t* Bh = &bh[n >> 1][(n & 1) * 2];
                    const uint32_t* Bl = &bl[n >> 1][(n & 1) * 2];
                    mma_bf16(acc[s][n], ah[s], Bh);
                    mma_bf16(acc[s][n], al[s], Bh);
                    mma_bf16(acc[s][n], ah[s], Bl);
                }
            }
        }
        buf ^= 1;
    }

    // epilogue
    const int g = lane >> 2, t = lane & 3;
    #pragma unroll
    for (int s = 0; s < 2; s++) {
        #pragma unroll
        for (int n = 0; n < 4; n++) {
            int row = m0 + wm * 32 + s * 16 + g;
            int col = n0 + wn * 32 + n * 8 + 2 * t;
            if (col < OC) {
                if (row < M)
                    *(float2*)&Out[(size_t)row * OC + col] = make_float2(acc[s][n][0], acc[s][n][1]);
                if (row + 8 < M)
                    *(float2*)&Out[(size_t)(row + 8) * OC + col] = make_float2(acc[s][n][2], acc[s][n][3]);
            }
        }
    }
}

// ---------------- scalar GEMM (tiny relation highway gate) ----------------
__global__ void k_gemm(const float* __restrict__ A, const float* __restrict__ W,
                       float* __restrict__ Out, int M, int K, int OC) {
    extern __shared__ float sm[];
    float* As = sm;
    float* Ws = sm + 64 * K;
    const int n0 = blockIdx.x * 64, o0 = blockIdx.y * 64;
    const int tid = threadIdx.x;
    const int Kv4 = K >> 2;

    for (int idx = tid; idx < 64 * Kv4; idx += 256) {
        int r = idx / Kv4, k4 = idx - r * Kv4;
        float4 v = make_float4(0.f, 0.f, 0.f, 0.f);
        if (n0 + r < M) v = *(const float4*)&A[(size_t)(n0 + r) * K + k4 * 4];
        *(float4*)&As[r * K + k4 * 4] = v;
    }
    for (int idx = tid; idx < 64 * Kv4; idx += 256) {
        int r = idx / Kv4, k4 = idx - r * Kv4;
        float4 v = make_float4(0.f, 0.f, 0.f, 0.f);
        if (o0 + r < OC) v = *(const float4*)&W[(size_t)(o0 + r) * K + k4 * 4];
        *(float4*)&Ws[r * K + k4 * 4] = v;
    }
    __syncthreads();

    const int tx = tid & 15, ty = tid >> 4;
    const float* Ap = &As[(ty * 4) * K];
    const float* Wp = &Ws[(tx * 4) * K];
    float acc[4][4] = {};
    #pragma unroll 4
    for (int k = 0; k < K; k++) {
        float a0 = Ap[k], a1 = Ap[K + k], a2 = Ap[2 * K + k], a3 = Ap[3 * K + k];
        float w0 = Wp[k], w1 = Wp[K + k], w2 = Wp[2 * K + k], w3 = Wp[3 * K + k];
        acc[0][0] += a0 * w0; acc[0][1] += a0 * w1; acc[0][2] += a0 * w2; acc[0][3] += a0 * w3;
        acc[1][0] += a1 * w0; acc[1][1] += a1 * w1; acc[1][2] += a1 * w2; acc[1][3] += a1 * w3;
        acc[2][0] += a2 * w0; acc[2][1] += a2 * w1; acc[2][2] += a2 * w2; acc[2][3] += a2 * w3;
        acc[3][0] += a3 * w0; acc[3][1] += a3 * w1; acc[3][2] += a3 * w2; acc[3][3] += a3 * w3;
    }
    #pragma unroll
    for (int q = 0; q < 4; q++) {
        int row = n0 + ty * 4 + q;
        if (row >= M) continue;
        #pragma unroll
        for (int p = 0; p < 4; p++) {
            int col = o0 + tx * 4 + p;
            if (col < OC) Out[(size_t)row * OC + col] = acc[q][p];
        }
    }
}

// ---------------- small utility kernels ----------------
__global__ void k_fill_ms(float* m, float* s, int n) {
    int i = blockIdx.x * 256 + threadIdx.x;
    if (i < n) { m[i] = __int_as_float(0xff800000); s[i] = 0.f; }
}
__global__ void k_relu(float* p, int n) {
    int i = blockIdx.x * 256 + threadIdx.x;
    if (i < n) p[i] = fmaxf(p[i], 0.f);
}
__global__ void k_deg(const int* __restrict__ ei, int nE, int* __restrict__ deg) {
    int e = blockIdx.x * 256 + threadIdx.x;
    if (e < nE) atomicAdd(&deg[ei[e]], 1);
}
__global__ void k_dinv(const int* __restrict__ deg, float* __restrict__ dinv, int n) {
    int i = blockIdx.x * 256 + threadIdx.x;
    if (i < n) { int d = deg[i]; dinv[i] = d > 0 ? rsqrtf((float)d) : 0.f; }
}

// ---------------- GCN edge aggregation ----------------
__global__ void k_gcn_agg(const int* __restrict__ ej, const int* __restrict__ ei,
                          const float* __restrict__ dinv, const float* __restrict__ xw,
                          float* __restrict__ agg, int nE) {
    int w = (blockIdx.x * blockDim.x + threadIdx.x) >> 5;
    int lane = threadIdx.x & 31;
    if (w >= nE) return;
    int j = ej[w], i = ei[w];
    float norm = dinv[j] * dinv[i];
    const float4* src = (const float4*)&xw[(size_t)j * EHID];
    float* dst = &agg[(size_t)i * EHID];
    for (int c4 = lane; c4 < EHID / 4; c4 += 32) {
        float4 v = src[c4];
        redAdd4(dst + c4 * 4, norm * v.x, norm * v.y, norm * v.z, norm * v.w);
    }
}

// ---------------- highway kernels ----------------
__global__ void k_highway_big(const float* __restrict__ gate, const float* __restrict__ bias,
                              const float* __restrict__ x1, const float* __restrict__ agg,
                              float* __restrict__ xout, float* __restrict__ dout) {
    int idx = blockIdx.x * 256 + threadIdx.x;
    if (idx >= NN * EHID) return;
    int c = idx % EHID;
    float g = sigf(gate[idx] + bias[c]);
    float a = fmaxf(agg[idx], 0.f);
    float v = g * a + (1.f - g) * x1[idx];
    xout[idx] = v;
    if (dout) { int n = idx / EHID; dout[(size_t)n * OUTW + c] = v; }
}

__global__ void k_highway_r(const float* __restrict__ gate, const float* __restrict__ bias,
                            const float* __restrict__ x1, const float* __restrict__ x2,
                            float* __restrict__ out, int n, int C) {
    int idx = blockIdx.x * 256 + threadIdx.x;
    if (idx >= n * C) return;
    int c = idx % C;
    float g = sigf(gate[idx] + bias[c]);
    out[idx] = g * x2[idx] + (1.f - g) * x1[idx];
}

// ---------------- l_gat passes ----------------
__global__ void k_lgat_p1(const int* __restrict__ ej, const int* __restrict__ ei,
                          const float* __restrict__ val, float* mi, float* mj, int nE) {
    int e = blockIdx.x * 256 + threadIdx.x;
    if (e >= nE) return;
    float v = val[e];
    atomicMaxF(&mi[ei[e]], v);
    atomicMaxF(&mj[ej[e]], v);
}
__global__ void k_lgat_p2(const int* __restrict__ ej, const int* __restrict__ ei,
                          const float* __restrict__ val, const float* __restrict__ mi,
                          const float* __restrict__ mj, float* si, float* sj, int nE) {
    int e = blockIdx.x * 256 + threadIdx.x;
    if (e >= nE) return;
    float v = val[e];
    atomicAdd(&si[ei[e]], expf(v - mi[ei[e]]));
    atomicAdd(&sj[ej[e]], expf(v - mj[ej[e]]));
}
__global__ void k_lgat_p3(const int* __restrict__ ej, const int* __restrict__ ei,
                          const float* __restrict__ val,
                          const float* __restrict__ mi, const float* __restrict__ si,
                          const float* __restrict__ mj, const float* __restrict__ sj,
                          float* m3, float* tbuf, int nE) {
    int e = blockIdx.x * 256 + threadIdx.x;
    if (e >= nE) return;
    int i = ei[e], j = ej[e];
    float v = val[e];
    float vi = expf(v - mi[i]) / (si[i] + 1e-16f);
    float vj = expf(v - mj[j]) / (sj[j] + 1e-16f);
    float t = vi + vj;
    tbuf[e] = t;
    atomicMaxF(&m3[j], t);
}
__global__ void k_lgat_p4(const int* __restrict__ ej, const float* __restrict__ tbuf,
                          const float* __restrict__ m3, float* s3, float* pbuf, int nE) {
    int e = blockIdx.x * 256 + threadIdx.x;
    if (e >= nE) return;
    float p = expf(tbuf[e] - m3[ej[e]]);
    pbuf[e] = p;
    atomicAdd(&s3[ej[e]], p);
}
__global__ void k_lgat_p5(const int* __restrict__ ej, const int* __restrict__ ei,
                          const float* __restrict__ pbuf, const float* __restrict__ s3,
                          const float* __restrict__ x, float* __restrict__ outb, int nE) {
    int w = (blockIdx.x * blockDim.x + threadIdx.x) >> 5;
    int lane = threadIdx.x & 31;
    if (w >= nE) return;
    int j = ej[w], i = ei[w];
    float alpha = pbuf[w] / (s3[j] + 1e-16f);
    if (lane < RHD / 4) {
        float4 v = ((const float4*)&x[(size_t)j * RHD])[lane];
        redAdd4(&outb[(size_t)i * RHD + lane * 4], alpha * v.x, alpha * v.y, alpha * v.z, alpha * v.w);
    }
}

// ---------------- per-node / per-row dot products ----------------
__global__ void k_node_dots2(const float* __restrict__ X, int stride, int len,
                             const float* __restrict__ va, const float* __restrict__ vb,
                             float* __restrict__ oa, float* __restrict__ ob, int n) {
    int w = (blockIdx.x * blockDim.x + threadIdx.x) >> 5;
    int lane = threadIdx.x & 31;
    if (w >= n) return;
    const float* row = X + (size_t)w * stride;
    float sa = 0.f, sb = 0.f;
    for (int c = lane; c < len; c += 32) { float x = row[c]; sa += x * va[c]; sb += x * vb[c]; }
    sa = warpSum(sa); sb = warpSum(sb);
    if (lane == 0) { oa[w] = sa; ob[w] = sb; }
}
__global__ void k_dot_rows(const float* __restrict__ X, int stride, int len,
                           const float* __restrict__ v, float* __restrict__ out, int n) {
    int w = (blockIdx.x * blockDim.x + threadIdx.x) >> 5;
    int lane = threadIdx.x & 31;
    if (w >= n) return;
    const float* row = X + (size_t)w * stride;
    float s = 0.f;
    for (int c = lane; c < len; c += 32) s += row[c] * v[c];
    s = warpSum(s);
    if (lane == 0) out[w] = s;
}
__global__ void k_rcar(const float* __restrict__ mrg, const float* __restrict__ tri,
                       const float* __restrict__ ar, float* __restrict__ rcar) {
    int w = (blockIdx.x * blockDim.x + threadIdx.x) >> 5;
    int lane = threadIdx.x & 31;
    if (w >= RRN) return;
    float s = 0.f;
    for (int c = lane; c < RHD; c += 32)
        s += mrg[(size_t)w * RHD + c] * ar[c] + tri[(size_t)w * RHD + c] * ar[RHD + c];
    s = warpSum(s);
    if (lane == 0) rcar[w] = s;
}

// ---------------- GAT over edge_index_all ----------------
__global__ void k_gat_p1(const int* __restrict__ ej, const int* __restrict__ ei,
                         const int* __restrict__ ra, const float* __restrict__ xa,
                         const float* __restrict__ xb, const float* __restrict__ rcar,
                         float* __restrict__ ebuf, float* m, int nE) {
    int e = blockIdx.x * 256 + threadIdx.x;
    if (e >= nE) return;
    int i = ei[e], j = ej[e];
    int rr = ra[e]; if (rr >= RRN) rr -= RRN;
    float v = lrelu(xa[i] + xb[j] + rcar[rr]);
    ebuf[e] = v;
    atomicMaxF(&m[i], v);
}
__global__ void k_seg_exp(const int* __restrict__ idx, float* __restrict__ ebuf,
                          const float* __restrict__ m, float* s, int nE) {
    int e = blockIdx.x * 256 + threadIdx.x;
    if (e >= nE) return;
    int g = idx[e];
    float p = expf(ebuf[e] - m[g]);
    ebuf[e] = p;
    atomicAdd(&s[g], p);
}
__global__ void k_gat_p3(const int* __restrict__ ej, const int* __restrict__ ei,
                         const float* __restrict__ pbuf, const float* __restrict__ s,
                         const float* __restrict__ x, float* __restrict__ agg, int nE) {
    int w = (blockIdx.x * blockDim.x + threadIdx.x) >> 5;
    int lane = threadIdx.x & 31;
    if (w >= nE) return;
    int j = ej[w], i = ei[w];
    float alpha = pbuf[w] / (s[i] + 1e-16f);
    const float4* src = (const float4*)&x[(size_t)j * EHID];
    float* dst = &agg[(size_t)i * EHID];
    for (int c4 = lane; c4 < EHID / 4; c4 += 32) {
        float4 v = src[c4];
        redAdd4(dst + c4 * 4, alpha * v.x, alpha * v.y, alpha * v.z, alpha * v.w);
    }
}
__global__ void k_concat_gat(const float* __restrict__ agg, float* __restrict__ out) {
    int idx = blockIdx.x * 256 + threadIdx.x;
    if (idx >= NN * EHID) return;
    int n = idx / EHID, c = idx - n * EHID;
    out[(size_t)n * OUTW + 300 + c] = fmaxf(agg[idx], 0.f);
    if (c < 200) out[(size_t)n * OUTW + 600 + c] = 0.f;
}

// ---------------- gat_r_to_e ----------------
__global__ void k_g2e_p1(const int* __restrict__ eh, const int* __restrict__ et,
                         const int* __restrict__ rel, const float* __restrict__ xh,
                         const float* __restrict__ xt, const float* __restrict__ er,
                         float* __restrict__ e1, float* __restrict__ e2,
                         float* m1, float* m2, int nE) {
    int e = blockIdx.x * 256 + threadIdx.x;
    if (e >= nE) return;
    int h = eh[e], t = et[e], r = rel[e];
    float w = er[r];
    float a = lrelu(xh[h] + w);
    float b = lrelu(xt[t] + w);
    e1[e] = a; e2[e] = b;
    atomicMaxF(&m1[h], a);
    atomicMaxF(&m2[t], b);
}
__global__ void k_g2e_p3(const int* __restrict__ eh, const int* __restrict__ et,
                         const int* __restrict__ rel,
                         const float* __restrict__ p1, const float* __restrict__ s1,
                         const float* __restrict__ p2, const float* __restrict__ s2,
                         const float* __restrict__ xr, float* __restrict__ out, int nE) {
    int w = (blockIdx.x * blockDim.x + threadIdx.x) >> 5;
    int lane = threadIdx.x & 31;
    if (w >= nE) return;
    int h = eh[w], t = et[w], r = rel[w];
    float a1 = p1[w] / (s1[h] + 1e-16f);
    float a2 = p2[w] / (s2[t] + 1e-16f);
    if (lane < RHD / 4) {
        float4 v = ((const float4*)&xr[(size_t)r * RHD])[lane];
        redAdd4(&out[(size_t)h * OUTW + 600 + lane * 4], a1 * v.x, a1 * v.y, a1 * v.z, a1 * v.w);
        redAdd4(&out[(size_t)t * OUTW + 700 + lane * 4], a2 * v.x, a2 * v.y, a2 * v.z, a2 * v.w);
    }
}

// ---------------- host ----------------
static inline int TPE(int n) { return (n + 255) / 256; }
static inline int WPE(int n) { return (n + 7) / 8; }

extern "C" void kernel_launch(void* const* d_in, const int* in_sizes, int n_in,
                              void* d_out_v, int out_size) {
    const float* x_e       = (const float*)d_in[0];
    const float* merge_val = (const float*)d_in[1];
    const float* tri_val   = (const float*)d_in[2];
    const float* gcn1_w    = (const float*)d_in[3];
    const float* hw1_w     = (const float*)d_in[4];
    const float* hw1_b     = (const float*)d_in[5];
    const float* gcn2_w    = (const float*)d_in[6];
    const float* hw2_w     = (const float*)d_in[7];
    const float* hw2_b     = (const float*)d_in[8];
    const float* rel_out1  = (const float*)d_in[9];
    const float* rel_tri1  = (const float*)d_in[10];
    const float* hwr_w     = (const float*)d_in[11];
    const float* hwr_b     = (const float*)d_in[12];
    const float* gat_ai    = (const float*)d_in[13];
    const float* gat_aj    = (const float*)d_in[14];
    const float* gat_ar    = (const float*)d_in[15];
    const float* g2e_ah    = (const float*)d_in[16];
    const float* g2e_at    = (const float*)d_in[17];
    const float* g2e_ar    = (const float*)d_in[18];
    const int*   ei        = (const int*)d_in[19];
    const int*   rel       = (const int*)d_in[20];
    const int*   ei_all    = (const int*)d_in[21];
    const int*   rel_all   = (const int*)d_in[22];
    const int*   lg_merge  = (const int*)d_in[23];
    const int*   lg_tri    = (const int*)d_in[24];
    float*       out       = (float*)d_out_v;

    float *p_xw, *p_agg, *p_x, *p_dinv, *p_m1, *p_s1, *p_m2, *p_s2, *p_na, *p_nb;
    float *p_e1, *p_e2, *p_rmerge, *p_rtri, *p_xr, *p_rgate, *p_rm, *p_rs, *p_lt, *p_lp, *p_rcar;
    int* p_deg;
    cudaGetSymbolAddress((void**)&p_xw, g_xw);
    cudaGetSymbolAddress((void**)&p_agg, g_agg);
    cudaGetSymbolAddress((void**)&p_x, g_x);
    cudaGetSymbolAddress((void**)&p_dinv, g_dinv);
    cudaGetSymbolAddress((void**)&p_deg, g_deg);
    cudaGetSymbolAddress((void**)&p_m1, g_m1);
    cudaGetSymbolAddress((void**)&p_s1, g_s1);
    cudaGetSymbolAddress((void**)&p_m2, g_m2);
    cudaGetSymbolAddress((void**)&p_s2, g_s2);
    cudaGetSymbolAddress((void**)&p_na, g_na);
    cudaGetSymbolAddress((void**)&p_nb, g_nb);
    cudaGetSymbolAddress((void**)&p_e1, g_e1);
    cudaGetSymbolAddress((void**)&p_e2, g_e2);
    cudaGetSymbolAddress((void**)&p_rmerge, g_rmerge);
    cudaGetSymbolAddress((void**)&p_rtri, g_rtri);
    cudaGetSymbolAddress((void**)&p_xr, g_xr);
    cudaGetSymbolAddress((void**)&p_rgate, g_rgate);
    cudaGetSymbolAddress((void**)&p_rm, g_rm);
    cudaGetSymbolAddress((void**)&p_rs, g_rs);
    cudaGetSymbolAddress((void**)&p_lt, g_lt);
    cudaGetSymbolAddress((void**)&p_lp, g_lp);
    cudaGetSymbolAddress((void**)&p_rcar, g_rcar);

    cudaFuncSetAttribute(k_gemm, cudaFuncAttributeMaxDynamicSharedMemorySize, 160 * 1024);
    cudaFuncSetAttribute(k_gemm_bf16, cudaFuncAttributeMaxDynamicSharedMemorySize, SMEM_GB);

    const size_t bigBytes = (size_t)NN * EHID * sizeof(float);
    const size_t smemR = 2 * 64 * RHD * sizeof(float);
    dim3 gB((NN + BBM - 1) / BBM, (EHID + BBN - 1) / BBN);   // (782, 5)
    dim3 gRel((RRN + 63) / 64, (RHD + 63) / 64);

    // ---- degrees ----
    cudaMemsetAsync(p_deg, 0, NN * sizeof(int), 0);
    k_deg<<<TPE(NE2), 256>>>(ei_all + NE2, NE2, p_deg);
    k_dinv<<<TPE(NN), 256>>>(p_deg, p_dinv, NN);

    // ---- GCN1 + highway1 ----
    k_gemm_bf16<<<gB, 256, SMEM_GB>>>(x_e, gcn1_w, p_xw, NN, EHID, EHID);
    cudaMemsetAsync(p_agg, 0, bigBytes, 0);
    k_gcn_agg<<<WPE(NE2), 256>>>(ei_all, ei_all + NE2, p_dinv, p_xw, p_agg, NE2);
    k_gemm_bf16<<<gB, 256, SMEM_GB>>>(x_e, hw1_w, p_xw, NN, EHID, EHID);
    k_highway_big<<<TPE(NN * EHID), 256>>>(p_xw, hw1_b, x_e, p_agg, p_x, (float*)0);

    // ---- GCN2 + highway2 ----
    k_gemm_bf16<<<gB, 256, SMEM_GB>>>(p_x, gcn2_w, p_xw, NN, EHID, EHID);
    cudaMemsetAsync(p_agg, 0, bigBytes, 0);
    k_gcn_agg<<<WPE(NE2), 256>>>(ei_all, ei_all + NE2, p_dinv, p_xw, p_agg, NE2);
    k_gemm_bf16<<<gB, 256, SMEM_GB>>>(p_x, hw2_w, p_xw, NN, EHID, EHID);
    k_highway_big<<<TPE(NN * EHID), 256>>>(p_xw, hw2_b, p_x, p_agg, p_x, out);

    // ---- relation l_gat (merge) ----
    {
        float *mi = p_rm, *mj = p_rm + RRN, *m3 = p_rm + 2 * RRN;
        float *si = p_rs, *sj = p_rs + RRN, *s3 = p_rs + 2 * RRN;
        k_fill_ms<<<TPE(3 * RRN), 256>>>(p_rm, p_rs, 3 * RRN);
        cudaMemsetAsync(p_rmerge, 0, RRN * RHD * sizeof(float), 0);
        k_lgat_p1<<<TPE(LGEN), 256>>>(lg_merge, lg_merge + LGEN, merge_val, mi, mj, LGEN);
        k_lgat_p2<<<TPE(LGEN), 256>>>(lg_merge, lg_merge + LGEN, merge_val, mi, mj, si, sj, LGEN);
        k_lgat_p3<<<TPE(LGEN), 256>>>(lg_merge, lg_merge + LGEN, merge_val, mi, si, mj, sj, m3, p_lt, LGEN);
        k_lgat_p4<<<TPE(LGEN), 256>>>(lg_merge, p_lt, m3, s3, p_lp, LGEN);
        k_lgat_p5<<<WPE(LGEN), 256>>>(lg_merge, lg_merge + LGEN, p_lp, s3, rel_out1, p_rmerge, LGEN);
        k_relu<<<TPE(RRN * RHD), 256>>>(p_rmerge, RRN * RHD);
    }
    // ---- relation l_gat (triangular) ----
    {
        float *mi = p_rm, *mj = p_rm + RRN, *m3 = p_rm + 2 * RRN;
        float *si = p_rs, *sj = p_rs + RRN, *s3 = p_rs + 2 * RRN;
        k_fill_ms<<<TPE(3 * RRN), 256>>>(p_rm, p_rs, 3 * RRN);
        cudaMemsetAsync(p_rtri, 0, RRN * RHD * sizeof(float), 0);
        k_lgat_p1<<<TPE(LGEN), 256>>>(lg_tri, lg_tri + LGEN, tri_val, mi, mj, LGEN);
        k_lgat_p2<<<TPE(LGEN), 256>>>(lg_tri, lg_tri + LGEN, tri_val, mi, mj, si, sj, LGEN);
        k_lgat_p3<<<TPE(LGEN), 256>>>(lg_tri, lg_tri + LGEN, tri_val, mi, si, mj, sj, m3, p_lt, LGEN);
        k_lgat_p4<<<TPE(LGEN), 256>>>(lg_tri, p_lt, m3, s3, p_lp, LGEN);
        k_lgat_p5<<<WPE(LGEN), 256>>>(lg_tri, lg_tri + LGEN, p_lp, s3, rel_tri1, p_rtri, LGEN);
        k_relu<<<TPE(RRN * RHD), 256>>>(p_rtri, RRN * RHD);
    }
    // ---- relation highway + projections ----
    k_gemm<<<gRel, 256, smemR>>>(p_rmerge, hwr_w, p_rgate, RRN, RHD, RHD);
    k_highway_r<<<TPE(RRN * RHD), 256>>>(p_rgate, hwr_b, p_rmerge, p_rtri, p_xr, RRN * RHD, RHD);
    k_rcar<<<WPE(RRN), 256>>>(p_rmerge, p_rtri, gat_ar, p_rcar);

    // ---- GAT over edge_index_all ----
    k_node_dots2<<<WPE(NN), 256>>>(p_x, EHID, EHID, gat_ai, gat_aj, p_na, p_nb, NN);
    k_fill_ms<<<TPE(NN), 256>>>(p_m1, p_s1, NN);
    cudaMemsetAsync(p_agg, 0, bigBytes, 0);
    k_gat_p1<<<TPE(NE2), 256>>>(ei_all, ei_all + NE2, rel_all, p_na, p_nb, p_rcar, p_e1, p_m1, NE2);
    k_seg_exp<<<TPE(NE2), 256>>>(ei_all + NE2, p_e1, p_m1, p_s1, NE2);
    k_gat_p3<<<WPE(NE2), 256>>>(ei_all, ei_all + NE2, p_e1, p_s1, p_x, p_agg, NE2);
    k_concat_gat<<<TPE(NN * EHID), 256>>>(p_agg, out);

    // ---- gat_r_to_e ----
    k_node_dots2<<<WPE(NN), 256>>>(out, OUTW, 600, g2e_ah, g2e_at, p_na, p_nb, NN);
    k_dot_rows<<<WPE(RRN), 256>>>(p_xr, RHD, RHD, g2e_ar, p_rcar, RRN);
    k_fill_ms<<<TPE(NN), 256>>>(p_m1, p_s1, NN);
    k_fill_ms<<<TPE(NN), 256>>>(p_m2, p_s2, NN);
    k_g2e_p1<<<TPE(NE1), 256>>>(ei, ei + NE1, rel, p_na, p_nb, p_rcar, p_e1, p_e2, p_m1, p_m2, NE1);
    k_seg_exp<<<TPE(NE1), 256>>>(ei, p_e1, p_m1, p_s1, NE1);
    k_seg_exp<<<TPE(NE1), 256>>>(ei + NE1, p_e2, p_m2, p_s2, NE1);
    k_g2e_p3<<<WPE(NE1), 256>>>(ei, ei + NE1, rel, p_e1, p_s1, p_e2, p_s2, p_xr, out, NE1);
}

// round 9
// speedup vs baseline: 5.7475x; 1.3653x over previous
#include <cuda_runtime.h>
#include <cuda_bf16.h>
#include <math.h>
#include <stddef.h>
#include <stdint.h>

#define NN    100000
#define EHID  300
#define NE1   400000
#define NE2   800000
#define RRN   2000
#define RHD   100
#define LGEN  60000
#define NEGS  0.01f
#define OUTW  800

// ---------------- device scratch ----------------
static __device__ float g_xw [(size_t)NN * EHID];
static __device__ float g_agg[(size_t)NN * EHID];
static __device__ float g_x  [(size_t)NN * EHID];
static __device__ float g_dinv[NN];
static __device__ int   g_deg [NN];
static __device__ int   g_off [NN + 1];
static __device__ int   g_posc[NN];
static __device__ int   g_bsum[512];
static __device__ int   g_csrj[NE2];
static __device__ int   g_csre[NE2];
static __device__ float g_m1[NN], g_s1[NN], g_m2[NN], g_s2[NN];
static __device__ float g_na[NN], g_nb[NN];
static __device__ float g_e1[NE2];
static __device__ float g_e2[NE1];
static __device__ float g_rmerge[RRN * RHD], g_rtri[RRN * RHD];
static __device__ float g_xr[RRN * RHD], g_rgate[RRN * RHD];
static __device__ float g_rm[3 * RRN], g_rs[3 * RRN];
static __device__ float g_lt[LGEN], g_lp[LGEN];
static __device__ float g_rcar[RRN];

// ---------------- generic device helpers ----------------
__device__ __forceinline__ void atomicMaxF(float* a, float v) {
    if (v >= 0.f) atomicMax((int*)a, __float_as_int(v));
    else          atomicMin((unsigned int*)a, __float_as_uint(v));
}
__device__ __forceinline__ void redAdd4(float* a, float x, float y, float z, float w) {
    asm volatile("red.global.add.v4.f32 [%0], {%1,%2,%3,%4};"
                 :: "l"(a), "f"(x), "f"(y), "f"(z), "f"(w) : "memory");
}
__device__ __forceinline__ float warpSum(float v) {
    #pragma unroll
    for (int o = 16; o; o >>= 1) v += __shfl_xor_sync(0xffffffffu, v, o);
    return v;
}
__device__ __forceinline__ float lrelu(float v) { return v > 0.f ? v : NEGS * v; }
__device__ __forceinline__ float sigf(float z)  { return 1.f / (1.f + expf(-z)); }

__device__ __forceinline__ uint32_t smem_u32(const void* p) {
    uint32_t a;
    asm("{ .reg .u64 t; cvta.to.shared.u64 t, %1; cvt.u32.u64 %0, t; }" : "=r"(a) : "l"(p));
    return a;
}
__device__ __forceinline__ void ldsm4(uint32_t* r, uint32_t addr) {
    asm volatile("ldmatrix.sync.aligned.m8n8.x4.shared.b16 {%0,%1,%2,%3}, [%4];"
                 : "=r"(r[0]), "=r"(r[1]), "=r"(r[2]), "=r"(r[3]) : "r"(addr));
}
__device__ __forceinline__ void mma_bf16(float* c, const uint32_t* a, const uint32_t* b) {
    asm volatile("mma.sync.aligned.m16n8k16.row.col.f32.bf16.bf16.f32 "
                 "{%0,%1,%2,%3},{%4,%5,%6,%7},{%8,%9},{%0,%1,%2,%3};"
                 : "+f"(c[0]), "+f"(c[1]), "+f"(c[2]), "+f"(c[3])
                 : "r"(a[0]), "r"(a[1]), "r"(a[2]), "r"(a[3]), "r"(b[0]), "r"(b[1]));
}

// ---------------- bf16 hi/lo 3-pass GEMM (unchanged from R6 WIN) ----------------
#define BBM 128
#define BBN 64
#define BBK 32
#define BST 40
#define SZ_A (BBM * BST * 2)
#define SZ_W (BBN * BST * 2)
#define BUFB (2 * SZ_A + 2 * SZ_W)
#define SMEM_GB (2 * BUFB)

__device__ __forceinline__ void cvt_hilo(float4 v, uint2& h, uint2& l) {
    __nv_bfloat16 h0 = __float2bfloat16(v.x), h1 = __float2bfloat16(v.y);
    __nv_bfloat16 h2 = __float2bfloat16(v.z), h3 = __float2bfloat16(v.w);
    __nv_bfloat16 l0 = __float2bfloat16(v.x - __bfloat162float(h0));
    __nv_bfloat16 l1 = __float2bfloat16(v.y - __bfloat162float(h1));
    __nv_bfloat16 l2 = __float2bfloat16(v.z - __bfloat162float(h2));
    __nv_bfloat16 l3 = __float2bfloat16(v.w - __bfloat162float(h3));
    __nv_bfloat162 ha = __halves2bfloat162(h0, h1), hb = __halves2bfloat162(h2, h3);
    __nv_bfloat162 la = __halves2bfloat162(l0, l1), lb = __halves2bfloat162(l2, l3);
    h = make_uint2(*(uint32_t*)&ha, *(uint32_t*)&hb);
    l = make_uint2(*(uint32_t*)&la, *(uint32_t*)&lb);
}

__global__ __launch_bounds__(256, 2)
void k_gemm_bf16(const float* __restrict__ A, const float* __restrict__ W,
                 float* __restrict__ Out, int M, int K, int OC) {
    extern __shared__ char smem[];
    const int tid = threadIdx.x, lane = tid & 31, wid = tid >> 5;
    const int wm = wid & 3, wn = wid >> 2;
    const int m0 = blockIdx.x * BBM, n0 = blockIdx.y * BBN;
    const int nch = (K + BBK - 1) / BBK;

    const uint32_t sbase = smem_u32(smem);

    float acc[2][4][4];
    #pragma unroll
    for (int s = 0; s < 2; s++)
        #pragma unroll
        for (int n = 0; n < 4; n++)
            #pragma unroll
            for (int q = 0; q < 4; q++) acc[s][n][q] = 0.f;

    float4 pa[4], pw[2];
    {
        int k0 = 0;
        #pragma unroll
        for (int q = 0; q < 4; q++) {
            int idx = q * 256 + tid, r = idx >> 3, c4 = (idx & 7) * 4;
            pa[q] = make_float4(0.f, 0.f, 0.f, 0.f);
            if (m0 + r < M && k0 + c4 < K) pa[q] = *(const float4*)&A[(size_t)(m0 + r) * K + k0 + c4];
        }
        #pragma unroll
        for (int q = 0; q < 2; q++) {
            int idx = q * 256 + tid, r = idx >> 3, c4 = (idx & 7) * 4;
            pw[q] = make_float4(0.f, 0.f, 0.f, 0.f);
            if (n0 + r < OC && k0 + c4 < K) pw[q] = *(const float4*)&W[(size_t)(n0 + r) * K + k0 + c4];
        }
    }

    const int lrow = lane & 7, lsel = lane >> 3;
    const int aRowB = wm * 32 + ((lsel & 1) << 3) + lrow;
    const int aColB = (lsel >> 1) << 3;
    const int bRowB = wn * 32 + ((lsel >> 1) << 3) + lrow;
    const int bColB = (lsel & 1) << 3;

    int buf = 0;
    for (int kt = 0; kt < nch; kt++) {
        char* sb = smem + buf * BUFB;
        char* sAh = sb;
        char* sAl = sb + SZ_A;
        char* sWh = sb + 2 * SZ_A;
        char* sWl = sb + 2 * SZ_A + SZ_W;

        #pragma unroll
        for (int q = 0; q < 4; q++) {
            int idx = q * 256 + tid, r = idx >> 3, c4 = (idx & 7) * 4;
            uint2 h, l; cvt_hilo(pa[q], h, l);
            *(uint2*)(sAh + (r * BST + c4) * 2) = h;
            *(uint2*)(sAl + (r * BST + c4) * 2) = l;
        }
        #pragma unroll
        for (int q = 0; q < 2; q++) {
            int idx = q * 256 + tid, r = idx >> 3, c4 = (idx & 7) * 4;
            uint2 h, l; cvt_hilo(pw[q], h, l);
            *(uint2*)(sWh + (r * BST + c4) * 2) = h;
            *(uint2*)(sWl + (r * BST + c4) * 2) = l;
        }
        __syncthreads();

        if (kt + 1 < nch) {
            int k0 = (kt + 1) * BBK;
            #pragma unroll
            for (int q = 0; q < 4; q++) {
                int idx = q * 256 + tid, r = idx >> 3, c4 = (idx & 7) * 4;
                pa[q] = make_float4(0.f, 0.f, 0.f, 0.f);
                if (m0 + r < M && k0 + c4 < K) pa[q] = *(const float4*)&A[(size_t)(m0 + r) * K + k0 + c4];
            }
            #pragma unroll
            for (int q = 0; q < 2; q++) {
                int idx = q * 256 + tid, r = idx >> 3, c4 = (idx & 7) * 4;
                pw[q] = make_float4(0.f, 0.f, 0.f, 0.f);
                if (n0 + r < OC && k0 + c4 < K) pw[q] = *(const float4*)&W[(size_t)(n0 + r) * K + k0 + c4];
            }
        }

        const uint32_t uAh = sbase + buf * BUFB;
        const uint32_t uAl = uAh + SZ_A;
        const uint32_t uWh = uAh + 2 * SZ_A;
        const uint32_t uWl = uWh + SZ_W;

        #pragma unroll
        for (int h = 0; h < 2; h++) {
            uint32_t ah[2][4], al[2][4], bh[2][4], bl[2][4];
            #pragma unroll
            for (int s = 0; s < 2; s++) {
                uint32_t off = ((aRowB + s * 16) * BST + h * 16 + aColB) * 2;
                ldsm4(ah[s], uAh + off);
                ldsm4(al[s], uAl + off);
            }
            #pragma unroll
            for (int p = 0; p < 2; p++) {
                uint32_t off = ((bRowB + p * 16) * BST + h * 16 + bColB) * 2;
                ldsm4(bh[p], uWh + off);
                ldsm4(bl[p], uWl + off);
            }
            #pragma unroll
            for (int s = 0; s < 2; s++) {
                #pragma unroll
                for (int n = 0; n < 4; n++) {
                    const uint32_t* Bh = &bh[n >> 1][(n & 1) * 2];
                    const uint32_t* Bl = &bl[n >> 1][(n & 1) * 2];
                    mma_bf16(acc[s][n], ah[s], Bh);
                    mma_bf16(acc[s][n], al[s], Bh);
                    mma_bf16(acc[s][n], ah[s], Bl);
                }
            }
        }
        buf ^= 1;
    }

    const int g = lane >> 2, t = lane & 3;
    #pragma unroll
    for (int s = 0; s < 2; s++) {
        #pragma unroll
        for (int n = 0; n < 4; n++) {
            int row = m0 + wm * 32 + s * 16 + g;
            int col = n0 + wn * 32 + n * 8 + 2 * t;
            if (col < OC) {
                if (row < M)
                    *(float2*)&Out[(size_t)row * OC + col] = make_float2(acc[s][n][0], acc[s][n][1]);
                if (row + 8 < M)
                    *(float2*)&Out[(size_t)(row + 8) * OC + col] = make_float2(acc[s][n][2], acc[s][n][3]);
            }
        }
    }
}

// ---------------- scalar GEMM (tiny relation highway gate) ----------------
__global__ void k_gemm(const float* __restrict__ A, const float* __restrict__ W,
                       float* __restrict__ Out, int M, int K, int OC) {
    extern __shared__ float sm[];
    float* As = sm;
    float* Ws = sm + 64 * K;
    const int n0 = blockIdx.x * 64, o0 = blockIdx.y * 64;
    const int tid = threadIdx.x;
    const int Kv4 = K >> 2;

    for (int idx = tid; idx < 64 * Kv4; idx += 256) {
        int r = idx / Kv4, k4 = idx - r * Kv4;
        float4 v = make_float4(0.f, 0.f, 0.f, 0.f);
        if (n0 + r < M) v = *(const float4*)&A[(size_t)(n0 + r) * K + k4 * 4];
        *(float4*)&As[r * K + k4 * 4] = v;
    }
    for (int idx = tid; idx < 64 * Kv4; idx += 256) {
        int r = idx / Kv4, k4 = idx - r * Kv4;
        float4 v = make_float4(0.f, 0.f, 0.f, 0.f);
        if (o0 + r < OC) v = *(const float4*)&W[(size_t)(o0 + r) * K + k4 * 4];
        *(float4*)&Ws[r * K + k4 * 4] = v;
    }
    __syncthreads();

    const int tx = tid & 15, ty = tid >> 4;
    const float* Ap = &As[(ty * 4) * K];
    const float* Wp = &Ws[(tx * 4) * K];
    float acc[4][4] = {};
    #pragma unroll 4
    for (int k = 0; k < K; k++) {
        float a0 = Ap[k], a1 = Ap[K + k], a2 = Ap[2 * K + k], a3 = Ap[3 * K + k];
        float w0 = Wp[k], w1 = Wp[K + k], w2 = Wp[2 * K + k], w3 = Wp[3 * K + k];
        acc[0][0] += a0 * w0; acc[0][1] += a0 * w1; acc[0][2] += a0 * w2; acc[0][3] += a0 * w3;
        acc[1][0] += a1 * w0; acc[1][1] += a1 * w1; acc[1][2] += a1 * w2; acc[1][3] += a1 * w3;
        acc[2][0] += a2 * w0; acc[2][1] += a2 * w1; acc[2][2] += a2 * w2; acc[2][3] += a2 * w3;
        acc[3][0] += a3 * w0; acc[3][1] += a3 * w1; acc[3][2] += a3 * w2; acc[3][3] += a3 * w3;
    }
    #pragma unroll
    for (int q = 0; q < 4; q++) {
        int row = n0 + ty * 4 + q;
        if (row >= M) continue;
        #pragma unroll
        for (int p = 0; p < 4; p++) {
            int col = o0 + tx * 4 + p;
            if (col < OC) Out[(size_t)row * OC + col] = acc[q][p];
        }
    }
}

// ---------------- small utility kernels ----------------
__global__ void k_fill_ms(float* m, float* s, int n) {
    int i = blockIdx.x * 256 + threadIdx.x;
    if (i < n) { m[i] = __int_as_float(0xff800000); s[i] = 0.f; }
}
__global__ void k_relu(float* p, int n) {
    int i = blockIdx.x * 256 + threadIdx.x;
    if (i < n) p[i] = fmaxf(p[i], 0.f);
}
__global__ void k_deg(const int* __restrict__ ei, int nE, int* __restrict__ deg) {
    int e = blockIdx.x * 256 + threadIdx.x;
    if (e < nE) atomicAdd(&deg[ei[e]], 1);
}
__global__ void k_dinv(const int* __restrict__ deg, float* __restrict__ dinv, int n) {
    int i = blockIdx.x * 256 + threadIdx.x;
    if (i < n) { int d = deg[i]; dinv[i] = d > 0 ? rsqrtf((float)d) : 0.f; }
}

// ---------------- CSR build: blocksum -> scan bsum -> final scan -> scatter ----------------
__global__ void k_blocksum(const int* __restrict__ deg, int* __restrict__ bsum, int n) {
    __shared__ int sh[256];
    int i = blockIdx.x * 256 + threadIdx.x;
    sh[threadIdx.x] = (i < n) ? deg[i] : 0;
    __syncthreads();
    #pragma unroll
    for (int o = 128; o; o >>= 1) {
        if (threadIdx.x < o) sh[threadIdx.x] += sh[threadIdx.x + o];
        __syncthreads();
    }
    if (threadIdx.x == 0) bsum[blockIdx.x] = sh[0];
}
__global__ void k_scan_bsum(int* __restrict__ bsum, int nb) {   // nb <= 512, 1 block of 512
    __shared__ int sh[512];
    int v = (threadIdx.x < nb) ? bsum[threadIdx.x] : 0;
    sh[threadIdx.x] = v;
    __syncthreads();
    for (int o = 1; o < 512; o <<= 1) {
        int t = (threadIdx.x >= o) ? sh[threadIdx.x - o] : 0;
        __syncthreads();
        sh[threadIdx.x] += t;
        __syncthreads();
    }
    if (threadIdx.x < nb) bsum[threadIdx.x] = sh[threadIdx.x] - v;   // exclusive
}
__global__ void k_scan_final(const int* __restrict__ deg, const int* __restrict__ bsum,
                             int* __restrict__ off, int* __restrict__ pos, int n) {
    __shared__ int sh[256];
    int i = blockIdx.x * 256 + threadIdx.x;
    int v = (i < n) ? deg[i] : 0;
    sh[threadIdx.x] = v;
    __syncthreads();
    for (int o = 1; o < 256; o <<= 1) {
        int t = (threadIdx.x >= o) ? sh[threadIdx.x - o] : 0;
        __syncthreads();
        sh[threadIdx.x] += t;
        __syncthreads();
    }
    int excl = sh[threadIdx.x] - v + bsum[blockIdx.x];
    if (i < n) { off[i] = excl; pos[i] = excl; }
    if (i == n - 1) off[n] = excl + v;
}
__global__ void k_scatter(const int* __restrict__ ej, const int* __restrict__ ei,
                          int* __restrict__ pos, int* __restrict__ csrj,
                          int* __restrict__ csre, int nE) {
    int e = blockIdx.x * 256 + threadIdx.x;
    if (e >= nE) return;
    int p = atomicAdd(&pos[ei[e]], 1);
    csrj[p] = ej[e];
    csre[p] = e;
}

// ---------------- CSR GCN aggregation: warp per node, write-once ----------------
__global__ __launch_bounds__(256)
void k_gcn_csr(const int* __restrict__ off, const int* __restrict__ csrj,
               const float* __restrict__ dinv, const float* __restrict__ xw,
               float* __restrict__ agg) {
    int node = blockIdx.x * 8 + (threadIdx.x >> 5);
    if (node >= NN) return;
    int lane = threadIdx.x & 31;
    int s = off[node], e = off[node + 1];
    float4 a0 = make_float4(0.f, 0.f, 0.f, 0.f), a1 = a0, a2 = a0;
    for (int p = s; p < e; p++) {
        int j = csrj[p];
        float w = dinv[j];
        const float4* src = (const float4*)&xw[(size_t)j * EHID];
        float4 v0 = src[lane];
        float4 v1 = src[lane + 32];
        a0.x += w * v0.x; a0.y += w * v0.y; a0.z += w * v0.z; a0.w += w * v0.w;
        a1.x += w * v1.x; a1.y += w * v1.y; a1.z += w * v1.z; a1.w += w * v1.w;
        if (lane < 11) {
            float4 v2 = src[lane + 64];
            a2.x += w * v2.x; a2.y += w * v2.y; a2.z += w * v2.z; a2.w += w * v2.w;
        }
    }
    float di = dinv[node];
    float4* dst = (float4*)&agg[(size_t)node * EHID];
    dst[lane]      = make_float4(di * a0.x, di * a0.y, di * a0.z, di * a0.w);
    dst[lane + 32] = make_float4(di * a1.x, di * a1.y, di * a1.z, di * a1.w);
    if (lane < 11)
        dst[lane + 64] = make_float4(di * a2.x, di * a2.y, di * a2.z, di * a2.w);
}

// ---------------- CSR GAT aggregation: relu(sum) -> d_out[:,300:600], zero [:,600:800] ----------------
__global__ __launch_bounds__(256)
void k_gat_csr(const int* __restrict__ off, const int* __restrict__ csrj,
               const int* __restrict__ csre, const float* __restrict__ pbuf,
               const float* __restrict__ ssum, const float* __restrict__ x,
               float* __restrict__ out) {
    int node = blockIdx.x * 8 + (threadIdx.x >> 5);
    if (node >= NN) return;
    int lane = threadIdx.x & 31;
    int s = off[node], e = off[node + 1];
    float rs = 1.f / (ssum[node] + 1e-16f);
    float4 a0 = make_float4(0.f, 0.f, 0.f, 0.f), a1 = a0, a2 = a0;
    for (int p = s; p < e; p++) {
        int j = csrj[p];
        float alpha = pbuf[csre[p]] * rs;
        const float4* src = (const float4*)&x[(size_t)j * EHID];
        float4 v0 = src[lane];
        float4 v1 = src[lane + 32];
        a0.x += alpha * v0.x; a0.y += alpha * v0.y; a0.z += alpha * v0.z; a0.w += alpha * v0.w;
        a1.x += alpha * v1.x; a1.y += alpha * v1.y; a1.z += alpha * v1.z; a1.w += alpha * v1.w;
        if (lane < 11) {
            float4 v2 = src[lane + 64];
            a2.x += alpha * v2.x; a2.y += alpha * v2.y; a2.z += alpha * v2.z; a2.w += alpha * v2.w;
        }
    }
    float4* dst = (float4*)&out[(size_t)node * OUTW + 300];
    dst[lane]      = make_float4(fmaxf(a0.x, 0.f), fmaxf(a0.y, 0.f), fmaxf(a0.z, 0.f), fmaxf(a0.w, 0.f));
    dst[lane + 32] = make_float4(fmaxf(a1.x, 0.f), fmaxf(a1.y, 0.f), fmaxf(a1.z, 0.f), fmaxf(a1.w, 0.f));
    if (lane < 11)
        dst[lane + 64] = make_float4(fmaxf(a2.x, 0.f), fmaxf(a2.y, 0.f), fmaxf(a2.z, 0.f), fmaxf(a2.w, 0.f));
    // zero cols [600,800) = 50 float4 slots
    float4* dz = (float4*)&out[(size_t)node * OUTW + 600];
    float4 z = make_float4(0.f, 0.f, 0.f, 0.f);
    dz[lane] = z;
    if (lane < 18) dz[lane + 32] = z;
}

// ---------------- highway kernels ----------------
__global__ void k_highway_big(const float* __restrict__ gate, const float* __restrict__ bias,
                              const float* __restrict__ x1, const float* __restrict__ agg,
                              float* __restrict__ xout, float* __restrict__ dout) {
    int idx = blockIdx.x * 256 + threadIdx.x;
    if (idx >= NN * EHID) return;
    int c = idx % EHID;
    float g = sigf(gate[idx] + bias[c]);
    float a = fmaxf(agg[idx], 0.f);
    float v = g * a + (1.f - g) * x1[idx];
    xout[idx] = v;
    if (dout) { int n = idx / EHID; dout[(size_t)n * OUTW + c] = v; }
}

__global__ void k_highway_r(const float* __restrict__ gate, const float* __restrict__ bias,
                            const float* __restrict__ x1, const float* __restrict__ x2,
                            float* __restrict__ out, int n, int C) {
    int idx = blockIdx.x * 256 + threadIdx.x;
    if (idx >= n * C) return;
    int c = idx % C;
    float g = sigf(gate[idx] + bias[c]);
    out[idx] = g * x2[idx] + (1.f - g) * x1[idx];
}

// ---------------- l_gat passes ----------------
__global__ void k_lgat_p1(const int* __restrict__ ej, const int* __restrict__ ei,
                          const float* __restrict__ val, float* mi, float* mj, int nE) {
    int e = blockIdx.x * 256 + threadIdx.x;
    if (e >= nE) return;
    float v = val[e];
    atomicMaxF(&mi[ei[e]], v);
    atomicMaxF(&mj[ej[e]], v);
}
__global__ void k_lgat_p2(const int* __restrict__ ej, const int* __restrict__ ei,
                          const float* __restrict__ val, const float* __restrict__ mi,
                          const float* __restrict__ mj, float* si, float* sj, int nE) {
    int e = blockIdx.x * 256 + threadIdx.x;
    if (e >= nE) return;
    float v = val[e];
    atomicAdd(&si[ei[e]], expf(v - mi[ei[e]]));
    atomicAdd(&sj[ej[e]], expf(v - mj[ej[e]]));
}
__global__ void k_lgat_p3(const int* __restrict__ ej, const int* __restrict__ ei,
                          const float* __restrict__ val,
                          const float* __restrict__ mi, const float* __restrict__ si,
                          const float* __restrict__ mj, const float* __restrict__ sj,
                          float* m3, float* tbuf, int nE) {
    int e = blockIdx.x * 256 + threadIdx.x;
    if (e >= nE) return;
    int i = ei[e], j = ej[e];
    float v = val[e];
    float vi = expf(v - mi[i]) / (si[i] + 1e-16f);
    float vj = expf(v - mj[j]) / (sj[j] + 1e-16f);
    float t = vi + vj;
    tbuf[e] = t;
    atomicMaxF(&m3[j], t);
}
__global__ void k_lgat_p4(const int* __restrict__ ej, const float* __restrict__ tbuf,
                          const float* __restrict__ m3, float* s3, float* pbuf, int nE) {
    int e = blockIdx.x * 256 + threadIdx.x;
    if (e >= nE) return;
    float p = expf(tbuf[e] - m3[ej[e]]);
    pbuf[e] = p;
    atomicAdd(&s3[ej[e]], p);
}
__global__ void k_lgat_p5(const int* __restrict__ ej, const int* __restrict__ ei,
                          const float* __restrict__ pbuf, const float* __restrict__ s3,
                          const float* __restrict__ x, float* __restrict__ outb, int nE) {
    int w = (blockIdx.x * blockDim.x + threadIdx.x) >> 5;
    int lane = threadIdx.x & 31;
    if (w >= nE) return;
    int j = ej[w], i = ei[w];
    float alpha = pbuf[w] / (s3[j] + 1e-16f);
    if (lane < RHD / 4) {
        float4 v = ((const float4*)&x[(size_t)j * RHD])[lane];
        redAdd4(&outb[(size_t)i * RHD + lane * 4], alpha * v.x, alpha * v.y, alpha * v.z, alpha * v.w);
    }
}

// ---------------- per-node / per-row dot products ----------------
__global__ void k_node_dots2(const float* __restrict__ X, int stride, int len,
                             const float* __restrict__ va, const float* __restrict__ vb,
                             float* __restrict__ oa, float* __restrict__ ob, int n) {
    int w = (blockIdx.x * blockDim.x + threadIdx.x) >> 5;
    int lane = threadIdx.x & 31;
    if (w >= n) return;
    const float* row = X + (size_t)w * stride;
    float sa = 0.f, sb = 0.f;
    for (int c = lane; c < len; c += 32) { float x = row[c]; sa += x * va[c]; sb += x * vb[c]; }
    sa = warpSum(sa); sb = warpSum(sb);
    if (lane == 0) { oa[w] = sa; ob[w] = sb; }
}
__global__ void k_dot_rows(const float* __restrict__ X, int stride, int len,
                           const float* __restrict__ v, float* __restrict__ out, int n) {
    int w = (blockIdx.x * blockDim.x + threadIdx.x) >> 5;
    int lane = threadIdx.x & 31;
    if (w >= n) return;
    const float* row = X + (size_t)w * stride;
    float s = 0.f;
    for (int c = lane; c < len; c += 32) s += row[c] * v[c];
    s = warpSum(s);
    if (lane == 0) out[w] = s;
}
__global__ void k_rcar(const float* __restrict__ mrg, const float* __restrict__ tri,
                       const float* __restrict__ ar, float* __restrict__ rcar) {
    int w = (blockIdx.x * blockDim.x + threadIdx.x) >> 5;
    int lane = threadIdx.x & 31;
    if (w >= RRN) return;
    float s = 0.f;
    for (int c = lane; c < RHD; c += 32)
        s += mrg[(size_t)w * RHD + c] * ar[c] + tri[(size_t)w * RHD + c] * ar[RHD + c];
    s = warpSum(s);
    if (lane == 0) rcar[w] = s;
}

// ---------------- GAT edge-score passes ----------------
__global__ void k_gat_p1(const int* __restrict__ ej, const int* __restrict__ ei,
                         const int* __restrict__ ra, const float* __restrict__ xa,
                         const float* __restrict__ xb, const float* __restrict__ rcar,
                         float* __restrict__ ebuf, float* m, int nE) {
    int e = blockIdx.x * 256 + threadIdx.x;
    if (e >= nE) return;
    int i = ei[e], j = ej[e];
    int rr = ra[e]; if (rr >= RRN) rr -= RRN;
    float v = lrelu(xa[i] + xb[j] + rcar[rr]);
    ebuf[e] = v;
    atomicMaxF(&m[i], v);
}
__global__ void k_seg_exp(const int* __restrict__ idx, float* __restrict__ ebuf,
                          const float* __restrict__ m, float* s, int nE) {
    int e = blockIdx.x * 256 + threadIdx.x;
    if (e >= nE) return;
    int g = idx[e];
    float p = expf(ebuf[e] - m[g]);
    ebuf[e] = p;
    atomicAdd(&s[g], p);
}

// ---------------- gat_r_to_e ----------------
__global__ void k_g2e_p1(const int* __restrict__ eh, const int* __restrict__ et,
                         const int* __restrict__ rel, const float* __restrict__ xh,
                         const float* __restrict__ xt, const float* __restrict__ er,
                         float* __restrict__ e1, float* __restrict__ e2,
                         float* m1, float* m2, int nE) {
    int e = blockIdx.x * 256 + threadIdx.x;
    if (e >= nE) return;
    int h = eh[e], t = et[e], r = rel[e];
    float w = er[r];
    float a = lrelu(xh[h] + w);
    float b = lrelu(xt[t] + w);
    e1[e] = a; e2[e] = b;
    atomicMaxF(&m1[h], a);
    atomicMaxF(&m2[t], b);
}
__global__ void k_g2e_p3(const int* __restrict__ eh, const int* __restrict__ et,
                         const int* __restrict__ rel,
                         const float* __restrict__ p1, const float* __restrict__ s1,
                         const float* __restrict__ p2, const float* __restrict__ s2,
                         const float* __restrict__ xr, float* __restrict__ out, int nE) {
    int w = (blockIdx.x * blockDim.x + threadIdx.x) >> 5;
    int lane = threadIdx.x & 31;
    if (w >= nE) return;
    int h = eh[w], t = et[w], r = rel[w];
    float a1 = p1[w] / (s1[h] + 1e-16f);
    float a2 = p2[w] / (s2[t] + 1e-16f);
    if (lane < RHD / 4) {
        float4 v = ((const float4*)&xr[(size_t)r * RHD])[lane];
        redAdd4(&out[(size_t)h * OUTW + 600 + lane * 4], a1 * v.x, a1 * v.y, a1 * v.z, a1 * v.w);
        redAdd4(&out[(size_t)t * OUTW + 700 + lane * 4], a2 * v.x, a2 * v.y, a2 * v.z, a2 * v.w);
    }
}

// ---------------- host ----------------
static inline int TPE(int n) { return (n + 255) / 256; }
static inline int WPE(int n) { return (n + 7) / 8; }

extern "C" void kernel_launch(void* const* d_in, const int* in_sizes, int n_in,
                              void* d_out_v, int out_size) {
    const float* x_e       = (const float*)d_in[0];
    const float* merge_val = (const float*)d_in[1];
    const float* tri_val   = (const float*)d_in[2];
    const float* gcn1_w    = (const float*)d_in[3];
    const float* hw1_w     = (const float*)d_in[4];
    const float* hw1_b     = (const float*)d_in[5];
    const float* gcn2_w    = (const float*)d_in[6];
    const float* hw2_w     = (const float*)d_in[7];
    const float* hw2_b     = (const float*)d_in[8];
    const float* rel_out1  = (const float*)d_in[9];
    const float* rel_tri1  = (const float*)d_in[10];
    const float* hwr_w     = (const float*)d_in[11];
    const float* hwr_b     = (const float*)d_in[12];
    const float* gat_ai    = (const float*)d_in[13];
    const float* gat_aj    = (const float*)d_in[14];
    const float* gat_ar    = (const float*)d_in[15];
    const float* g2e_ah    = (const float*)d_in[16];
    const float* g2e_at    = (const float*)d_in[17];
    const float* g2e_ar    = (const float*)d_in[18];
    const int*   ei        = (const int*)d_in[19];
    const int*   rel       = (const int*)d_in[20];
    const int*   ei_all    = (const int*)d_in[21];
    const int*   rel_all   = (const int*)d_in[22];
    const int*   lg_merge  = (const int*)d_in[23];
    const int*   lg_tri    = (const int*)d_in[24];
    float*       out       = (float*)d_out_v;

    float *p_xw, *p_agg, *p_x, *p_dinv, *p_m1, *p_s1, *p_m2, *p_s2, *p_na, *p_nb;
    float *p_e1, *p_e2, *p_rmerge, *p_rtri, *p_xr, *p_rgate, *p_rm, *p_rs, *p_lt, *p_lp, *p_rcar;
    int *p_deg, *p_off, *p_pos, *p_bsum, *p_csrj, *p_csre;
    cudaGetSymbolAddress((void**)&p_xw, g_xw);
    cudaGetSymbolAddress((void**)&p_agg, g_agg);
    cudaGetSymbolAddress((void**)&p_x, g_x);
    cudaGetSymbolAddress((void**)&p_dinv, g_dinv);
    cudaGetSymbolAddress((void**)&p_deg, g_deg);
    cudaGetSymbolAddress((void**)&p_off, g_off);
    cudaGetSymbolAddress((void**)&p_pos, g_posc);
    cudaGetSymbolAddress((void**)&p_bsum, g_bsum);
    cudaGetSymbolAddress((void**)&p_csrj, g_csrj);
    cudaGetSymbolAddress((void**)&p_csre, g_csre);
    cudaGetSymbolAddress((void**)&p_m1, g_m1);
    cudaGetSymbolAddress((void**)&p_s1, g_s1);
    cudaGetSymbolAddress((void**)&p_m2, g_m2);
    cudaGetSymbolAddress((void**)&p_s2, g_s2);
    cudaGetSymbolAddress((void**)&p_na, g_na);
    cudaGetSymbolAddress((void**)&p_nb, g_nb);
    cudaGetSymbolAddress((void**)&p_e1, g_e1);
    cudaGetSymbolAddress((void**)&p_e2, g_e2);
    cudaGetSymbolAddress((void**)&p_rmerge, g_rmerge);
    cudaGetSymbolAddress((void**)&p_rtri, g_rtri);
    cudaGetSymbolAddress((void**)&p_xr, g_xr);
    cudaGetSymbolAddress((void**)&p_rgate, g_rgate);
    cudaGetSymbolAddress((void**)&p_rm, g_rm);
    cudaGetSymbolAddress((void**)&p_rs, g_rs);
    cudaGetSymbolAddress((void**)&p_lt, g_lt);
    cudaGetSymbolAddress((void**)&p_lp, g_lp);
    cudaGetSymbolAddress((void**)&p_rcar, g_rcar);

    cudaFuncSetAttribute(k_gemm, cudaFuncAttributeMaxDynamicSharedMemorySize, 160 * 1024);
    cudaFuncSetAttribute(k_gemm_bf16, cudaFuncAttributeMaxDynamicSharedMemorySize, SMEM_GB);

    const size_t smemR = 2 * 64 * RHD * sizeof(float);
    dim3 gB((NN + BBM - 1) / BBM, (EHID + BBN - 1) / BBN);   // (782, 5)
    dim3 gRel((RRN + 63) / 64, (RHD + 63) / 64);
    const int nScanB = TPE(NN);   // 391 blocks

    // ---- degrees + CSR over edge_index_all (i = row 1) ----
    cudaMemsetAsync(p_deg, 0, NN * sizeof(int), 0);
    k_deg<<<TPE(NE2), 256>>>(ei_all + NE2, NE2, p_deg);
    k_dinv<<<TPE(NN), 256>>>(p_deg, p_dinv, NN);
    k_blocksum<<<nScanB, 256>>>(p_deg, p_bsum, NN);
    k_scan_bsum<<<1, 512>>>(p_bsum, nScanB);
    k_scan_final<<<nScanB, 256>>>(p_deg, p_bsum, p_off, p_pos, NN);
    k_scatter<<<TPE(NE2), 256>>>(ei_all, ei_all + NE2, p_pos, p_csrj, p_csre, NE2);

    // ---- GCN1 + highway1 ----
    k_gemm_bf16<<<gB, 256, SMEM_GB>>>(x_e, gcn1_w, p_xw, NN, EHID, EHID);
    k_gcn_csr<<<WPE(NN), 256>>>(p_off, p_csrj, p_dinv, p_xw, p_agg);
    k_gemm_bf16<<<gB, 256, SMEM_GB>>>(x_e, hw1_w, p_xw, NN, EHID, EHID);
    k_highway_big<<<TPE(NN * EHID), 256>>>(p_xw, hw1_b, x_e, p_agg, p_x, (float*)0);

    // ---- GCN2 + highway2 ----
    k_gemm_bf16<<<gB, 256, SMEM_GB>>>(p_x, gcn2_w, p_xw, NN, EHID, EHID);
    k_gcn_csr<<<WPE(NN), 256>>>(p_off, p_csrj, p_dinv, p_xw, p_agg);
    k_gemm_bf16<<<gB, 256, SMEM_GB>>>(p_x, hw2_w, p_xw, NN, EHID, EHID);
    k_highway_big<<<TPE(NN * EHID), 256>>>(p_xw, hw2_b, p_x, p_agg, p_x, out);

    // ---- relation l_gat (merge) ----
    {
        float *mi = p_rm, *mj = p_rm + RRN, *m3 = p_rm + 2 * RRN;
        float *si = p_rs, *sj = p_rs + RRN, *s3 = p_rs + 2 * RRN;
        k_fill_ms<<<TPE(3 * RRN), 256>>>(p_rm, p_rs, 3 * RRN);
        cudaMemsetAsync(p_rmerge, 0, RRN * RHD * sizeof(float), 0);
        k_lgat_p1<<<TPE(LGEN), 256>>>(lg_merge, lg_merge + LGEN, merge_val, mi, mj, LGEN);
        k_lgat_p2<<<TPE(LGEN), 256>>>(lg_merge, lg_merge + LGEN, merge_val, mi, mj, si, sj, LGEN);
        k_lgat_p3<<<TPE(LGEN), 256>>>(lg_merge, lg_merge + LGEN, merge_val, mi, si, mj, sj, m3, p_lt, LGEN);
        k_lgat_p4<<<TPE(LGEN), 256>>>(lg_merge, p_lt, m3, s3, p_lp, LGEN);
        k_lgat_p5<<<WPE(LGEN), 256>>>(lg_merge, lg_merge + LGEN, p_lp, s3, rel_out1, p_rmerge, LGEN);
        k_relu<<<TPE(RRN * RHD), 256>>>(p_rmerge, RRN * RHD);
    }
    // ---- relation l_gat (triangular) ----
    {
        float *mi = p_rm, *mj = p_rm + RRN, *m3 = p_rm + 2 * RRN;
        float *si = p_rs, *sj = p_rs + RRN, *s3 = p_rs + 2 * RRN;
        k_fill_ms<<<TPE(3 * RRN), 256>>>(p_rm, p_rs, 3 * RRN);
        cudaMemsetAsync(p_rtri, 0, RRN * RHD * sizeof(float), 0);
        k_lgat_p1<<<TPE(LGEN), 256>>>(lg_tri, lg_tri + LGEN, tri_val, mi, mj, LGEN);
        k_lgat_p2<<<TPE(LGEN), 256>>>(lg_tri, lg_tri + LGEN, tri_val, mi, mj, si, sj, LGEN);
        k_lgat_p3<<<TPE(LGEN), 256>>>(lg_tri, lg_tri + LGEN, tri_val, mi, si, mj, sj, m3, p_lt, LGEN);
        k_lgat_p4<<<TPE(LGEN), 256>>>(lg_tri, p_lt, m3, s3, p_lp, LGEN);
        k_lgat_p5<<<WPE(LGEN), 256>>>(lg_tri, lg_tri + LGEN, p_lp, s3, rel_tri1, p_rtri, LGEN);
        k_relu<<<TPE(RRN * RHD), 256>>>(p_rtri, RRN * RHD);
    }
    // ---- relation highway + projections ----
    k_gemm<<<gRel, 256, smemR>>>(p_rmerge, hwr_w, p_rgate, RRN, RHD, RHD);
    k_highway_r<<<TPE(RRN * RHD), 256>>>(p_rgate, hwr_b, p_rmerge, p_rtri, p_xr, RRN * RHD, RHD);
    k_rcar<<<WPE(RRN), 256>>>(p_rmerge, p_rtri, gat_ar, p_rcar);

    // ---- GAT over edge_index_all (CSR aggregation) ----
    k_node_dots2<<<WPE(NN), 256>>>(p_x, EHID, EHID, gat_ai, gat_aj, p_na, p_nb, NN);
    k_fill_ms<<<TPE(NN), 256>>>(p_m1, p_s1, NN);
    k_gat_p1<<<TPE(NE2), 256>>>(ei_all, ei_all + NE2, rel_all, p_na, p_nb, p_rcar, p_e1, p_m1, NE2);
    k_seg_exp<<<TPE(NE2), 256>>>(ei_all + NE2, p_e1, p_m1, p_s1, NE2);
    k_gat_csr<<<WPE(NN), 256>>>(p_off, p_csrj, p_csre, p_e1, p_s1, p_x, out);

    // ---- gat_r_to_e ----
    k_node_dots2<<<WPE(NN), 256>>>(out, OUTW, 600, g2e_ah, g2e_at, p_na, p_nb, NN);
    k_dot_rows<<<WPE(RRN), 256>>>(p_xr, RHD, RHD, g2e_ar, p_rcar, RRN);
    k_fill_ms<<<TPE(NN), 256>>>(p_m1, p_s1, NN);
    k_fill_ms<<<TPE(NN), 256>>>(p_m2, p_s2, NN);
    k_g2e_p1<<<TPE(NE1), 256>>>(ei, ei + NE1, rel, p_na, p_nb, p_rcar, p_e1, p_e2, p_m1, p_m2, NE1);
    k_seg_exp<<<TPE(NE1), 256>>>(ei, p_e1, p_m1, p_s1, NE1);
    k_seg_exp<<<TPE(NE1), 256>>>(ei + NE1, p_e2, p_m2, p_s2, NE1);
    k_g2e_p3<<<WPE(NE1), 256>>>(ei, ei + NE1, rel, p_e1, p_s1, p_e2, p_s2, p_xr, out, NE1);
}

// round 11
// speedup vs baseline: 6.3241x; 1.1003x over previous
#include <cuda_runtime.h>
#include <cuda_bf16.h>
#include <math.h>
#include <stddef.h>
#include <stdint.h>

#define NN    100000
#define EHID  300
#define NE1   400000
#define NE2   800000
#define RRN   2000
#define RHD   100
#define LGEN  60000
#define NEGS  0.01f
#define OUTW  800

// ---------------- device scratch ----------------
static __device__ float g_xw [(size_t)NN * EHID];
static __device__ float g_agg[(size_t)NN * EHID];
static __device__ float g_x  [(size_t)NN * EHID];
static __device__ float g_dinv[NN];
static __device__ int   g_deg [NN];
static __device__ int   g_off [NN + 1];
static __device__ int   g_posc[NN];
static __device__ int   g_bsum[512];
static __device__ int   g_csrj[NE2];
static __device__ int   g_csre[NE2];
static __device__ float g_m1[NN], g_s1[NN], g_m2[NN], g_s2[NN];
static __device__ float g_na[NN], g_nb[NN];
static __device__ float g_e1[NE2];
static __device__ float g_e2[NE1];
static __device__ float g_rmerge[RRN * RHD], g_rtri[RRN * RHD];
static __device__ float g_xr[RRN * RHD], g_rgate[RRN * RHD];
static __device__ float g_rm[3 * RRN], g_rs[3 * RRN];
static __device__ float g_lt[LGEN], g_lp[LGEN];
static __device__ float g_rcar[RRN];

// ---------------- generic device helpers ----------------
__device__ __forceinline__ void atomicMaxF(float* a, float v) {
    if (v >= 0.f) atomicMax((int*)a, __float_as_int(v));
    else          atomicMin((unsigned int*)a, __float_as_uint(v));
}
__device__ __forceinline__ void redAdd4(float* a, float x, float y, float z, float w) {
    asm volatile("red.global.add.v4.f32 [%0], {%1,%2,%3,%4};"
                 :: "l"(a), "f"(x), "f"(y), "f"(z), "f"(w) : "memory");
}
__device__ __forceinline__ float warpSum(float v) {
    #pragma unroll
    for (int o = 16; o; o >>= 1) v += __shfl_xor_sync(0xffffffffu, v, o);
    return v;
}
__device__ __forceinline__ float lrelu(float v) { return v > 0.f ? v : NEGS * v; }
__device__ __forceinline__ float sigf(float z)  { return 1.f / (1.f + expf(-z)); }

__device__ __forceinline__ uint32_t smem_u32(const void* p) {
    uint32_t a;
    asm("{ .reg .u64 t; cvta.to.shared.u64 t, %1; cvt.u32.u64 %0, t; }" : "=r"(a) : "l"(p));
    return a;
}
__device__ __forceinline__ void ldsm4(uint32_t* r, uint32_t addr) {
    asm volatile("ldmatrix.sync.aligned.m8n8.x4.shared.b16 {%0,%1,%2,%3}, [%4];"
                 : "=r"(r[0]), "=r"(r[1]), "=r"(r[2]), "=r"(r[3]) : "r"(addr));
}
__device__ __forceinline__ void mma_bf16(float* c, const uint32_t* a, const uint32_t* b) {
    asm volatile("mma.sync.aligned.m16n8k16.row.col.f32.bf16.bf16.f32 "
                 "{%0,%1,%2,%3},{%4,%5,%6,%7},{%8,%9},{%0,%1,%2,%3};"
                 : "+f"(c[0]), "+f"(c[1]), "+f"(c[2]), "+f"(c[3])
                 : "r"(a[0]), "r"(a[1]), "r"(a[2]), "r"(a[3]), "r"(b[0]), "r"(b[1]));
}

// ---------------- bf16 hi/lo 3-pass GEMM ----------------
// grid = (col-tiles, row-tiles): col tiles of one row group co-resident -> A hits L2.
// Optional fused highway epilogue: g=sig(acc+b); v=g*relu(agg)+(1-g)*x1 -> xout (+dout).
#define BBM 128
#define BBN 64
#define BBK 32
#define BST 40
#define SZ_A (BBM * BST * 2)
#define SZ_W (BBN * BST * 2)
#define BUFB (2 * SZ_A + 2 * SZ_W)
#define SMEM_GB (2 * BUFB)

__device__ __forceinline__ void cvt_hilo(float4 v, uint2& h, uint2& l) {
    __nv_bfloat16 h0 = __float2bfloat16(v.x), h1 = __float2bfloat16(v.y);
    __nv_bfloat16 h2 = __float2bfloat16(v.z), h3 = __float2bfloat16(v.w);
    __nv_bfloat16 l0 = __float2bfloat16(v.x - __bfloat162float(h0));
    __nv_bfloat16 l1 = __float2bfloat16(v.y - __bfloat162float(h1));
    __nv_bfloat16 l2 = __float2bfloat16(v.z - __bfloat162float(h2));
    __nv_bfloat16 l3 = __float2bfloat16(v.w - __bfloat162float(h3));
    __nv_bfloat162 ha = __halves2bfloat162(h0, h1), hb = __halves2bfloat162(h2, h3);
    __nv_bfloat162 la = __halves2bfloat162(l0, l1), lb = __halves2bfloat162(l2, l3);
    h = make_uint2(*(uint32_t*)&ha, *(uint32_t*)&hb);
    l = make_uint2(*(uint32_t*)&la, *(uint32_t*)&lb);
}

__global__ __launch_bounds__(256, 2)
void k_gemm_bf16(const float* __restrict__ A, const float* __restrict__ W,
                 float* __restrict__ Out, int M, int K, int OC,
                 const float* __restrict__ hb, const float* __restrict__ hx1,
                 const float* __restrict__ hagg, float* __restrict__ hxout,
                 float* __restrict__ hdout) {
    extern __shared__ char smem[];
    const int tid = threadIdx.x, lane = tid & 31, wid = tid >> 5;
    const int wm = wid & 3, wn = wid >> 2;
    const int m0 = blockIdx.y * BBM, n0 = blockIdx.x * BBN;   // col tiles in x (L2 reuse of A)
    const int nch = (K + BBK - 1) / BBK;

    const uint32_t sbase = smem_u32(smem);

    float acc[2][4][4];
    #pragma unroll
    for (int s = 0; s < 2; s++)
        #pragma unroll
        for (int n = 0; n < 4; n++)
            #pragma unroll
            for (int q = 0; q < 4; q++) acc[s][n][q] = 0.f;

    float4 pa[4], pw[2];
    {
        int k0 = 0;
        #pragma unroll
        for (int q = 0; q < 4; q++) {
            int idx = q * 256 + tid, r = idx >> 3, c4 = (idx & 7) * 4;
            pa[q] = make_float4(0.f, 0.f, 0.f, 0.f);
            if (m0 + r < M && k0 + c4 < K) pa[q] = *(const float4*)&A[(size_t)(m0 + r) * K + k0 + c4];
        }
        #pragma unroll
        for (int q = 0; q < 2; q++) {
            int idx = q * 256 + tid, r = idx >> 3, c4 = (idx & 7) * 4;
            pw[q] = make_float4(0.f, 0.f, 0.f, 0.f);
            if (n0 + r < OC && k0 + c4 < K) pw[q] = *(const float4*)&W[(size_t)(n0 + r) * K + k0 + c4];
        }
    }

    const int lrow = lane & 7, lsel = lane >> 3;
    const int aRowB = wm * 32 + ((lsel & 1) << 3) + lrow;
    const int aColB = (lsel >> 1) << 3;
    const int bRowB = wn * 32 + ((lsel >> 1) << 3) + lrow;
    const int bColB = (lsel & 1) << 3;

    int buf = 0;
    for (int kt = 0; kt < nch; kt++) {
        char* sb = smem + buf * BUFB;
        char* sAh = sb;
        char* sAl = sb + SZ_A;
        char* sWh = sb + 2 * SZ_A;
        char* sWl = sb + 2 * SZ_A + SZ_W;

        #pragma unroll
        for (int q = 0; q < 4; q++) {
            int idx = q * 256 + tid, r = idx >> 3, c4 = (idx & 7) * 4;
            uint2 h, l; cvt_hilo(pa[q], h, l);
            *(uint2*)(sAh + (r * BST + c4) * 2) = h;
            *(uint2*)(sAl + (r * BST + c4) * 2) = l;
        }
        #pragma unroll
        for (int q = 0; q < 2; q++) {
            int idx = q * 256 + tid, r = idx >> 3, c4 = (idx & 7) * 4;
            uint2 h, l; cvt_hilo(pw[q], h, l);
            *(uint2*)(sWh + (r * BST + c4) * 2) = h;
            *(uint2*)(sWl + (r * BST + c4) * 2) = l;
        }
        __syncthreads();

        if (kt + 1 < nch) {
            int k0 = (kt + 1) * BBK;
            #pragma unroll
            for (int q = 0; q < 4; q++) {
                int idx = q * 256 + tid, r = idx >> 3, c4 = (idx & 7) * 4;
                pa[q] = make_float4(0.f, 0.f, 0.f, 0.f);
                if (m0 + r < M && k0 + c4 < K) pa[q] = *(const float4*)&A[(size_t)(m0 + r) * K + k0 + c4];
            }
            #pragma unroll
            for (int q = 0; q < 2; q++) {
                int idx = q * 256 + tid, r = idx >> 3, c4 = (idx & 7) * 4;
                pw[q] = make_float4(0.f, 0.f, 0.f, 0.f);
                if (n0 + r < OC && k0 + c4 < K) pw[q] = *(const float4*)&W[(size_t)(n0 + r) * K + k0 + c4];
            }
        }

        const uint32_t uAh = sbase + buf * BUFB;
        const uint32_t uAl = uAh + SZ_A;
        const uint32_t uWh = uAh + 2 * SZ_A;
        const uint32_t uWl = uWh + SZ_W;

        #pragma unroll
        for (int h = 0; h < 2; h++) {
            uint32_t ah[2][4], al[2][4], bh[2][4], bl[2][4];
            #pragma unroll
            for (int s = 0; s < 2; s++) {
                uint32_t off = ((aRowB + s * 16) * BST + h * 16 + aColB) * 2;
                ldsm4(ah[s], uAh + off);
                ldsm4(al[s], uAl + off);
            }
            #pragma unroll
            for (int p = 0; p < 2; p++) {
                uint32_t off = ((bRowB + p * 16) * BST + h * 16 + bColB) * 2;
                ldsm4(bh[p], uWh + off);
                ldsm4(bl[p], uWl + off);
            }
            #pragma unroll
            for (int s = 0; s < 2; s++) {
                #pragma unroll
                for (int n = 0; n < 4; n++) {
                    const uint32_t* Bh = &bh[n >> 1][(n & 1) * 2];
                    const uint32_t* Bl = &bl[n >> 1][(n & 1) * 2];
                    mma_bf16(acc[s][n], ah[s], Bh);
                    mma_bf16(acc[s][n], al[s], Bh);
                    mma_bf16(acc[s][n], ah[s], Bl);
                }
            }
        }
        buf ^= 1;
    }

    const int g = lane >> 2, t = lane & 3;
    if (hb == 0) {
        // plain epilogue
        #pragma unroll
        for (int s = 0; s < 2; s++) {
            #pragma unroll
            for (int n = 0; n < 4; n++) {
                int row = m0 + wm * 32 + s * 16 + g;
                int col = n0 + wn * 32 + n * 8 + 2 * t;
                if (col < OC) {
                    if (row < M)
                        *(float2*)&Out[(size_t)row * OC + col] = make_float2(acc[s][n][0], acc[s][n][1]);
                    if (row + 8 < M)
                        *(float2*)&Out[(size_t)(row + 8) * OC + col] = make_float2(acc[s][n][2], acc[s][n][3]);
                }
            }
        }
    } else {
        // fused highway epilogue
        #pragma unroll
        for (int s = 0; s < 2; s++) {
            #pragma unroll
            for (int n = 0; n < 4; n++) {
                int row = m0 + wm * 32 + s * 16 + g;
                int col = n0 + wn * 32 + n * 8 + 2 * t;
                if (col >= OC) continue;
                float b0 = hb[col], b1 = hb[col + 1];
                #pragma unroll
                for (int hrow = 0; hrow < 2; hrow++) {
                    int rr = row + hrow * 8;
                    if (rr >= M) continue;
                    size_t base = (size_t)rr * OC + col;
                    float2 ag = *(const float2*)&hagg[base];
                    float2 x1 = *(const float2*)&hx1[base];
                    float g0 = sigf(acc[s][n][hrow * 2 + 0] + b0);
                    float g1 = sigf(acc[s][n][hrow * 2 + 1] + b1);
                    float v0 = g0 * fmaxf(ag.x, 0.f) + (1.f - g0) * x1.x;
                    float v1 = g1 * fmaxf(ag.y, 0.f) + (1.f - g1) * x1.y;
                    *(float2*)&hxout[base] = make_float2(v0, v1);
                    if (hdout) *(float2*)&hdout[(size_t)rr * OUTW + col] = make_float2(v0, v1);
                }
            }
        }
    }
}

// ---------------- scalar GEMM (tiny relation highway gate) ----------------
__global__ void k_gemm(const float* __restrict__ A, const float* __restrict__ W,
                       float* __restrict__ Out, int M, int K, int OC) {
    extern __shared__ float sm[];
    float* As = sm;
    float* Ws = sm + 64 * K;
    const int n0 = blockIdx.x * 64, o0 = blockIdx.y * 64;
    const int tid = threadIdx.x;
    const int Kv4 = K >> 2;

    for (int idx = tid; idx < 64 * Kv4; idx += 256) {
        int r = idx / Kv4, k4 = idx - r * Kv4;
        float4 v = make_float4(0.f, 0.f, 0.f, 0.f);
        if (n0 + r < M) v = *(const float4*)&A[(size_t)(n0 + r) * K + k4 * 4];
        *(float4*)&As[r * K + k4 * 4] = v;
    }
    for (int idx = tid; idx < 64 * Kv4; idx += 256) {
        int r = idx / Kv4, k4 = idx - r * Kv4;
        float4 v = make_float4(0.f, 0.f, 0.f, 0.f);
        if (o0 + r < OC) v = *(const float4*)&W[(size_t)(o0 + r) * K + k4 * 4];
        *(float4*)&Ws[r * K + k4 * 4] = v;
    }
    __syncthreads();

    const int tx = tid & 15, ty = tid >> 4;
    const float* Ap = &As[(ty * 4) * K];
    const float* Wp = &Ws[(tx * 4) * K];
    float acc[4][4] = {};
    #pragma unroll 4
    for (int k = 0; k < K; k++) {
        float a0 = Ap[k], a1 = Ap[K + k], a2 = Ap[2 * K + k], a3 = Ap[3 * K + k];
        float w0 = Wp[k], w1 = Wp[K + k], w2 = Wp[2 * K + k], w3 = Wp[3 * K + k];
        acc[0][0] += a0 * w0; acc[0][1] += a0 * w1; acc[0][2] += a0 * w2; acc[0][3] += a0 * w3;
        acc[1][0] += a1 * w0; acc[1][1] += a1 * w1; acc[1][2] += a1 * w2; acc[1][3] += a1 * w3;
        acc[2][0] += a2 * w0; acc[2][1] += a2 * w1; acc[2][2] += a2 * w2; acc[2][3] += a2 * w3;
        acc[3][0] += a3 * w0; acc[3][1] += a3 * w1; acc[3][2] += a3 * w2; acc[3][3] += a3 * w3;
    }
    #pragma unroll
    for (int q = 0; q < 4; q++) {
        int row = n0 + ty * 4 + q;
        if (row >= M) continue;
        #pragma unroll
        for (int p = 0; p < 4; p++) {
            int col = o0 + tx * 4 + p;
            if (col < OC) Out[(size_t)row * OC + col] = acc[q][p];
        }
    }
}

// ---------------- small utility kernels ----------------
__global__ void k_fill_ms(float* m, float* s, int n) {
    int i = blockIdx.x * 256 + threadIdx.x;
    if (i < n) { m[i] = __int_as_float(0xff800000); s[i] = 0.f; }
}
__global__ void k_relu(float* p, int n) {
    int i = blockIdx.x * 256 + threadIdx.x;
    if (i < n) p[i] = fmaxf(p[i], 0.f);
}
__global__ void k_deg(const int* __restrict__ ei, int nE, int* __restrict__ deg) {
    int e = blockIdx.x * 256 + threadIdx.x;
    if (e < nE) atomicAdd(&deg[ei[e]], 1);
}
__global__ void k_dinv(const int* __restrict__ deg, float* __restrict__ dinv, int n) {
    int i = blockIdx.x * 256 + threadIdx.x;
    if (i < n) { int d = deg[i]; dinv[i] = d > 0 ? rsqrtf((float)d) : 0.f; }
}

// ---------------- CSR build ----------------
__global__ void k_blocksum(const int* __restrict__ deg, int* __restrict__ bsum, int n) {
    __shared__ int sh[256];
    int i = blockIdx.x * 256 + threadIdx.x;
    sh[threadIdx.x] = (i < n) ? deg[i] : 0;
    __syncthreads();
    #pragma unroll
    for (int o = 128; o; o >>= 1) {
        if (threadIdx.x < o) sh[threadIdx.x] += sh[threadIdx.x + o];
        __syncthreads();
    }
    if (threadIdx.x == 0) bsum[blockIdx.x] = sh[0];
}
__global__ void k_scan_bsum(int* __restrict__ bsum, int nb) {
    __shared__ int sh[512];
    int v = (threadIdx.x < nb) ? bsum[threadIdx.x] : 0;
    sh[threadIdx.x] = v;
    __syncthreads();
    for (int o = 1; o < 512; o <<= 1) {
        int t = (threadIdx.x >= o) ? sh[threadIdx.x - o] : 0;
        __syncthreads();
        sh[threadIdx.x] += t;
        __syncthreads();
    }
    if (threadIdx.x < nb) bsum[threadIdx.x] = sh[threadIdx.x] - v;
}
__global__ void k_scan_final(const int* __restrict__ deg, const int* __restrict__ bsum,
                             int* __restrict__ off, int* __restrict__ pos, int n) {
    __shared__ int sh[256];
    int i = blockIdx.x * 256 + threadIdx.x;
    int v = (i < n) ? deg[i] : 0;
    sh[threadIdx.x] = v;
    __syncthreads();
    for (int o = 1; o < 256; o <<= 1) {
        int t = (threadIdx.x >= o) ? sh[threadIdx.x - o] : 0;
        __syncthreads();
        sh[threadIdx.x] += t;
        __syncthreads();
    }
    int excl = sh[threadIdx.x] - v + bsum[blockIdx.x];
    if (i < n) { off[i] = excl; pos[i] = excl; }
    if (i == n - 1) off[n] = excl + v;
}
__global__ void k_scatter(const int* __restrict__ ej, const int* __restrict__ ei,
                          int* __restrict__ pos, int* __restrict__ csrj,
                          int* __restrict__ csre, int nE) {
    int e = blockIdx.x * 256 + threadIdx.x;
    if (e >= nE) return;
    int p = atomicAdd(&pos[ei[e]], 1);
    csrj[p] = ej[e];
    csre[p] = e;
}

// ---------------- CSR GCN aggregation ----------------
__global__ __launch_bounds__(256)
void k_gcn_csr(const int* __restrict__ off, const int* __restrict__ csrj,
               const float* __restrict__ dinv, const float* __restrict__ xw,
               float* __restrict__ agg) {
    int node = blockIdx.x * 8 + (threadIdx.x >> 5);
    if (node >= NN) return;
    int lane = threadIdx.x & 31;
    int s = off[node], e = off[node + 1];
    float4 a0 = make_float4(0.f, 0.f, 0.f, 0.f), a1 = a0, a2 = a0;
    for (int p = s; p < e; p++) {
        int j = csrj[p];
        float w = dinv[j];
        const float4* src = (const float4*)&xw[(size_t)j * EHID];
        float4 v0 = src[lane];
        float4 v1 = src[lane + 32];
        a0.x += w * v0.x; a0.y += w * v0.y; a0.z += w * v0.z; a0.w += w * v0.w;
        a1.x += w * v1.x; a1.y += w * v1.y; a1.z += w * v1.z; a1.w += w * v1.w;
        if (lane < 11) {
            float4 v2 = src[lane + 64];
            a2.x += w * v2.x; a2.y += w * v2.y; a2.z += w * v2.z; a2.w += w * v2.w;
        }
    }
    float di = dinv[node];
    float4* dst = (float4*)&agg[(size_t)node * EHID];
    dst[lane]      = make_float4(di * a0.x, di * a0.y, di * a0.z, di * a0.w);
    dst[lane + 32] = make_float4(di * a1.x, di * a1.y, di * a1.z, di * a1.w);
    if (lane < 11)
        dst[lane + 64] = make_float4(di * a2.x, di * a2.y, di * a2.z, di * a2.w);
}

// ---------------- CSR GAT aggregation ----------------
__global__ __launch_bounds__(256)
void k_gat_csr(const int* __restrict__ off, const int* __restrict__ csrj,
               const int* __restrict__ csre, const float* __restrict__ pbuf,
               const float* __restrict__ ssum, const float* __restrict__ x,
               float* __restrict__ out) {
    int node = blockIdx.x * 8 + (threadIdx.x >> 5);
    if (node >= NN) return;
    int lane = threadIdx.x & 31;
    int s = off[node], e = off[node + 1];
    float rs = 1.f / (ssum[node] + 1e-16f);
    float4 a0 = make_float4(0.f, 0.f, 0.f, 0.f), a1 = a0, a2 = a0;
    for (int p = s; p < e; p++) {
        int j = csrj[p];
        float alpha = pbuf[csre[p]] * rs;
        const float4* src = (const float4*)&x[(size_t)j * EHID];
        float4 v0 = src[lane];
        float4 v1 = src[lane + 32];
        a0.x += alpha * v0.x; a0.y += alpha * v0.y; a0.z += alpha * v0.z; a0.w += alpha * v0.w;
        a1.x += alpha * v1.x; a1.y += alpha * v1.y; a1.z += alpha * v1.z; a1.w += alpha * v1.w;
        if (lane < 11) {
            float4 v2 = src[lane + 64];
            a2.x += alpha * v2.x; a2.y += alpha * v2.y; a2.z += alpha * v2.z; a2.w += alpha * v2.w;
        }
    }
    float4* dst = (float4*)&out[(size_t)node * OUTW + 300];
    dst[lane]      = make_float4(fmaxf(a0.x, 0.f), fmaxf(a0.y, 0.f), fmaxf(a0.z, 0.f), fmaxf(a0.w, 0.f));
    dst[lane + 32] = make_float4(fmaxf(a1.x, 0.f), fmaxf(a1.y, 0.f), fmaxf(a1.z, 0.f), fmaxf(a1.w, 0.f));
    if (lane < 11)
        dst[lane + 64] = make_float4(fmaxf(a2.x, 0.f), fmaxf(a2.y, 0.f), fmaxf(a2.z, 0.f), fmaxf(a2.w, 0.f));
    float4* dz = (float4*)&out[(size_t)node * OUTW + 600];
    float4 z = make_float4(0.f, 0.f, 0.f, 0.f);
    dz[lane] = z;
    if (lane < 18) dz[lane + 32] = z;
}

// ---------------- highway (relation-size only) ----------------
__global__ void k_highway_r(const float* __restrict__ gate, const float* __restrict__ bias,
                            const float* __restrict__ x1, const float* __restrict__ x2,
                            float* __restrict__ out, int n, int C) {
    int idx = blockIdx.x * 256 + threadIdx.x;
    if (idx >= n * C) return;
    int c = idx % C;
    float g = sigf(gate[idx] + bias[c]);
    out[idx] = g * x2[idx] + (1.f - g) * x1[idx];
}

// ---------------- l_gat passes ----------------
__global__ void k_lgat_p1(const int* __restrict__ ej, const int* __restrict__ ei,
                          const float* __restrict__ val, float* mi, float* mj, int nE) {
    int e = blockIdx.x * 256 + threadIdx.x;
    if (e >= nE) return;
    float v = val[e];
    atomicMaxF(&mi[ei[e]], v);
    atomicMaxF(&mj[ej[e]], v);
}
__global__ void k_lgat_p2(const int* __restrict__ ej, const int* __restrict__ ei,
                          const float* __restrict__ val, const float* __restrict__ mi,
                          const float* __restrict__ mj, float* si, float* sj, int nE) {
    int e = blockIdx.x * 256 + threadIdx.x;
    if (e >= nE) return;
    float v = val[e];
    atomicAdd(&si[ei[e]], expf(v - mi[ei[e]]));
    atomicAdd(&sj[ej[e]], expf(v - mj[ej[e]]));
}
__global__ void k_lgat_p3(const int* __restrict__ ej, const int* __restrict__ ei,
                          const float* __restrict__ val,
                          const float* __restrict__ mi, const float* __restrict__ si,
                          const float* __restrict__ mj, const float* __restrict__ sj,
                          float* m3, float* tbuf, int nE) {
    int e = blockIdx.x * 256 + threadIdx.x;
    if (e >= nE) return;
    int i = ei[e], j = ej[e];
    float v = val[e];
    float vi = expf(v - mi[i]) / (si[i] + 1e-16f);
    float vj = expf(v - mj[j]) / (sj[j] + 1e-16f);
    float t = vi + vj;
    tbuf[e] = t;
    atomicMaxF(&m3[j], t);
}
__global__ void k_lgat_p4(const int* __restrict__ ej, const float* __restrict__ tbuf,
                          const float* __restrict__ m3, float* s3, float* pbuf, int nE) {
    int e = blockIdx.x * 256 + threadIdx.x;
    if (e >= nE) return;
    float p = expf(tbuf[e] - m3[ej[e]]);
    pbuf[e] = p;
    atomicAdd(&s3[ej[e]], p);
}
__global__ void k_lgat_p5(const int* __restrict__ ej, const int* __restrict__ ei,
                          const float* __restrict__ pbuf, const float* __restrict__ s3,
                          const float* __restrict__ x, float* __restrict__ outb, int nE) {
    int w = (blockIdx.x * blockDim.x + threadIdx.x) >> 5;
    int lane = threadIdx.x & 31;
    if (w >= nE) return;
    int j = ej[w], i = ei[w];
    float alpha = pbuf[w] / (s3[j] + 1e-16f);
    if (lane < RHD / 4) {
        float4 v = ((const float4*)&x[(size_t)j * RHD])[lane];
        redAdd4(&outb[(size_t)i * RHD + lane * 4], alpha * v.x, alpha * v.y, alpha * v.z, alpha * v.w);
    }
}

// ---------------- per-node / per-row dot products ----------------
__global__ void k_node_dots2(const float* __restrict__ X, int stride, int len,
                             const float* __restrict__ va, const float* __restrict__ vb,
                             float* __restrict__ oa, float* __restrict__ ob, int n) {
    int w = (blockIdx.x * blockDim.x + threadIdx.x) >> 5;
    int lane = threadIdx.x & 31;
    if (w >= n) return;
    const float* row = X + (size_t)w * stride;
    float sa = 0.f, sb = 0.f;
    for (int c = lane; c < len; c += 32) { float x = row[c]; sa += x * va[c]; sb += x * vb[c]; }
    sa = warpSum(sa); sb = warpSum(sb);
    if (lane == 0) { oa[w] = sa; ob[w] = sb; }
}
__global__ void k_dot_rows(const float* __restrict__ X, int stride, int len,
                           const float* __restrict__ v, float* __restrict__ out, int n) {
    int w = (blockIdx.x * blockDim.x + threadIdx.x) >> 5;
    int lane = threadIdx.x & 31;
    if (w >= n) return;
    const float* row = X + (size_t)w * stride;
    float s = 0.f;
    for (int c = lane; c < len; c += 32) s += row[c] * v[c];
    s = warpSum(s);
    if (lane == 0) out[w] = s;
}
__global__ void k_rcar(const float* __restrict__ mrg, const float* __restrict__ tri,
                       const float* __restrict__ ar, float* __restrict__ rcar) {
    int w = (blockIdx.x * blockDim.x + threadIdx.x) >> 5;
    int lane = threadIdx.x & 31;
    if (w >= RRN) return;
    float s = 0.f;
    for (int c = lane; c < RHD; c += 32)
        s += mrg[(size_t)w * RHD + c] * ar[c] + tri[(size_t)w * RHD + c] * ar[RHD + c];
    s = warpSum(s);
    if (lane == 0) rcar[w] = s;
}

// ---------------- GAT edge-score passes ----------------
__global__ void k_gat_p1(const int* __restrict__ ej, const int* __restrict__ ei,
                         const int* __restrict__ ra, const float* __restrict__ xa,
                         const float* __restrict__ xb, const float* __restrict__ rcar,
                         float* __restrict__ ebuf, float* m, int nE) {
    int e = blockIdx.x * 256 + threadIdx.x;
    if (e >= nE) return;
    int i = ei[e], j = ej[e];
    int rr = ra[e]; if (rr >= RRN) rr -= RRN;
    float v = lrelu(xa[i] + xb[j] + rcar[rr]);
    ebuf[e] = v;
    atomicMaxF(&m[i], v);
}
__global__ void k_seg_exp(const int* __restrict__ idx, float* __restrict__ ebuf,
                          const float* __restrict__ m, float* s, int nE) {
    int e = blockIdx.x * 256 + threadIdx.x;
    if (e >= nE) return;
    int g = idx[e];
    float p = expf(ebuf[e] - m[g]);
    ebuf[e] = p;
    atomicAdd(&s[g], p);
}

// ---------------- gat_r_to_e ----------------
__global__ void k_g2e_p1(const int* __restrict__ eh, const int* __restrict__ et,
                         const int* __restrict__ rel, const float* __restrict__ xh,
                         const float* __restrict__ xt, const float* __restrict__ er,
                         float* __restrict__ e1, float* __restrict__ e2,
                         float* m1, float* m2, int nE) {
    int e = blockIdx.x * 256 + threadIdx.x;
    if (e >= nE) return;
    int h = eh[e], t = et[e], r = rel[e];
    float w = er[r];
    float a = lrelu(xh[h] + w);
    float b = lrelu(xt[t] + w);
    e1[e] = a; e2[e] = b;
    atomicMaxF(&m1[h], a);
    atomicMaxF(&m2[t], b);
}
__global__ void k_g2e_p3(const int* __restrict__ eh, const int* __restrict__ et,
                         const int* __restrict__ rel,
                         const float* __restrict__ p1, const float* __restrict__ s1,
                         const float* __restrict__ p2, const float* __restrict__ s2,
                         const float* __restrict__ xr, float* __restrict__ out, int nE) {
    int w = (blockIdx.x * blockDim.x + threadIdx.x) >> 5;
    int lane = threadIdx.x & 31;
    if (w >= nE) return;
    int h = eh[w], t = et[w], r = rel[w];
    float a1 = p1[w] / (s1[h] + 1e-16f);
    float a2 = p2[w] / (s2[t] + 1e-16f);
    if (lane < RHD / 4) {
        float4 v = ((const float4*)&xr[(size_t)r * RHD])[lane];
        redAdd4(&out[(size_t)h * OUTW + 600 + lane * 4], a1 * v.x, a1 * v.y, a1 * v.z, a1 * v.w);
        redAdd4(&out[(size_t)t * OUTW + 700 + lane * 4], a2 * v.x, a2 * v.y, a2 * v.z, a2 * v.w);
    }
}

// ---------------- host ----------------
static inline int TPE(int n) { return (n + 255) / 256; }
static inline int WPE(int n) { return (n + 7) / 8; }

extern "C" void kernel_launch(void* const* d_in, const int* in_sizes, int n_in,
                              void* d_out_v, int out_size) {
    const float* x_e       = (const float*)d_in[0];
    const float* merge_val = (const float*)d_in[1];
    const float* tri_val   = (const float*)d_in[2];
    const float* gcn1_w    = (const float*)d_in[3];
    const float* hw1_w     = (const float*)d_in[4];
    const float* hw1_b     = (const float*)d_in[5];
    const float* gcn2_w    = (const float*)d_in[6];
    const float* hw2_w     = (const float*)d_in[7];
    const float* hw2_b     = (const float*)d_in[8];
    const float* rel_out1  = (const float*)d_in[9];
    const float* rel_tri1  = (const float*)d_in[10];
    const float* hwr_w     = (const float*)d_in[11];
    const float* hwr_b     = (const float*)d_in[12];
    const float* gat_ai    = (const float*)d_in[13];
    const float* gat_aj    = (const float*)d_in[14];
    const float* gat_ar    = (const float*)d_in[15];
    const float* g2e_ah    = (const float*)d_in[16];
    const float* g2e_at    = (const float*)d_in[17];
    const float* g2e_ar    = (const float*)d_in[18];
    const int*   ei        = (const int*)d_in[19];
    const int*   rel       = (const int*)d_in[20];
    const int*   ei_all    = (const int*)d_in[21];
    const int*   rel_all   = (const int*)d_in[22];
    const int*   lg_merge  = (const int*)d_in[23];
    const int*   lg_tri    = (const int*)d_in[24];
    float*       out       = (float*)d_out_v;

    float *p_xw, *p_agg, *p_x, *p_dinv, *p_m1, *p_s1, *p_m2, *p_s2, *p_na, *p_nb;
    float *p_e1, *p_e2, *p_rmerge, *p_rtri, *p_xr, *p_rgate, *p_rm, *p_rs, *p_lt, *p_lp, *p_rcar;
    int *p_deg, *p_off, *p_pos, *p_bsum, *p_csrj, *p_csre;
    cudaGetSymbolAddress((void**)&p_xw, g_xw);
    cudaGetSymbolAddress((void**)&p_agg, g_agg);
    cudaGetSymbolAddress((void**)&p_x, g_x);
    cudaGetSymbolAddress((void**)&p_dinv, g_dinv);
    cudaGetSymbolAddress((void**)&p_deg, g_deg);
    cudaGetSymbolAddress((void**)&p_off, g_off);
    cudaGetSymbolAddress((void**)&p_pos, g_posc);
    cudaGetSymbolAddress((void**)&p_bsum, g_bsum);
    cudaGetSymbolAddress((void**)&p_csrj, g_csrj);
    cudaGetSymbolAddress((void**)&p_csre, g_csre);
    cudaGetSymbolAddress((void**)&p_m1, g_m1);
    cudaGetSymbolAddress((void**)&p_s1, g_s1);
    cudaGetSymbolAddress((void**)&p_m2, g_m2);
    cudaGetSymbolAddress((void**)&p_s2, g_s2);
    cudaGetSymbolAddress((void**)&p_na, g_na);
    cudaGetSymbolAddress((void**)&p_nb, g_nb);
    cudaGetSymbolAddress((void**)&p_e1, g_e1);
    cudaGetSymbolAddress((void**)&p_e2, g_e2);
    cudaGetSymbolAddress((void**)&p_rmerge, g_rmerge);
    cudaGetSymbolAddress((void**)&p_rtri, g_rtri);
    cudaGetSymbolAddress((void**)&p_xr, g_xr);
    cudaGetSymbolAddress((void**)&p_rgate, g_rgate);
    cudaGetSymbolAddress((void**)&p_rm, g_rm);
    cudaGetSymbolAddress((void**)&p_rs, g_rs);
    cudaGetSymbolAddress((void**)&p_lt, g_lt);
    cudaGetSymbolAddress((void**)&p_lp, g_lp);
    cudaGetSymbolAddress((void**)&p_rcar, g_rcar);

    cudaFuncSetAttribute(k_gemm, cudaFuncAttributeMaxDynamicSharedMemorySize, 160 * 1024);
    cudaFuncSetAttribute(k_gemm_bf16, cudaFuncAttributeMaxDynamicSharedMemorySize, SMEM_GB);

    const size_t smemR = 2 * 64 * RHD * sizeof(float);
    dim3 gB((EHID + BBN - 1) / BBN, (NN + BBM - 1) / BBM);   // (5, 782): col tiles fastest
    dim3 gRel((RRN + 63) / 64, (RHD + 63) / 64);
    const int nScanB = TPE(NN);

    // ---- degrees + CSR over edge_index_all (i = row 1) ----
    cudaMemsetAsync(p_deg, 0, NN * sizeof(int), 0);
    k_deg<<<TPE(NE2), 256>>>(ei_all + NE2, NE2, p_deg);
    k_dinv<<<TPE(NN), 256>>>(p_deg, p_dinv, NN);
    k_blocksum<<<nScanB, 256>>>(p_deg, p_bsum, NN);
    k_scan_bsum<<<1, 512>>>(p_bsum, nScanB);
    k_scan_final<<<nScanB, 256>>>(p_deg, p_bsum, p_off, p_pos, NN);
    k_scatter<<<TPE(NE2), 256>>>(ei_all, ei_all + NE2, p_pos, p_csrj, p_csre, NE2);

    // ---- GCN1 + fused highway1 ----
    k_gemm_bf16<<<gB, 256, SMEM_GB>>>(x_e, gcn1_w, p_xw, NN, EHID, EHID,
                                      (const float*)0, (const float*)0, (const float*)0,
                                      (float*)0, (float*)0);
    k_gcn_csr<<<WPE(NN), 256>>>(p_off, p_csrj, p_dinv, p_xw, p_agg);
    k_gemm_bf16<<<gB, 256, SMEM_GB>>>(x_e, hw1_w, p_xw, NN, EHID, EHID,
                                      hw1_b, x_e, p_agg, p_x, (float*)0);

    // ---- GCN2 + fused highway2 (x now lives in p_xw; also writes d_out[:,0:300]) ----
    k_gemm_bf16<<<gB, 256, SMEM_GB>>>(p_x, gcn2_w, p_xw, NN, EHID, EHID,
                                      (const float*)0, (const float*)0, (const float*)0,
                                      (float*)0, (float*)0);
    k_gcn_csr<<<WPE(NN), 256>>>(p_off, p_csrj, p_dinv, p_xw, p_agg);
    k_gemm_bf16<<<gB, 256, SMEM_GB>>>(p_x, hw2_w, p_x /*unused*/, NN, EHID, EHID,
                                      hw2_b, p_x, p_agg, p_xw, out);

    // ---- relation l_gat (merge) ----
    {
        float *mi = p_rm, *mj = p_rm + RRN, *m3 = p_rm + 2 * RRN;
        float *si = p_rs, *sj = p_rs + RRN, *s3 = p_rs + 2 * RRN;
        k_fill_ms<<<TPE(3 * RRN), 256>>>(p_rm, p_rs, 3 * RRN);
        cudaMemsetAsync(p_rmerge, 0, RRN * RHD * sizeof(float), 0);
        k_lgat_p1<<<TPE(LGEN), 256>>>(lg_merge, lg_merge + LGEN, merge_val, mi, mj, LGEN);
        k_lgat_p2<<<TPE(LGEN), 256>>>(lg_merge, lg_merge + LGEN, merge_val, mi, mj, si, sj, LGEN);
        k_lgat_p3<<<TPE(LGEN), 256>>>(lg_merge, lg_merge + LGEN, merge_val, mi, si, mj, sj, m3, p_lt, LGEN);
        k_lgat_p4<<<TPE(LGEN), 256>>>(lg_merge, p_lt, m3, s3, p_lp, LGEN);
        k_lgat_p5<<<WPE(LGEN), 256>>>(lg_merge, lg_merge + LGEN, p_lp, s3, rel_out1, p_rmerge, LGEN);
        k_relu<<<TPE(RRN * RHD), 256>>>(p_rmerge, RRN * RHD);
    }
    // ---- relation l_gat (triangular) ----
    {
        float *mi = p_rm, *mj = p_rm + RRN, *m3 = p_rm + 2 * RRN;
        float *si = p_rs, *sj = p_rs + RRN, *s3 = p_rs + 2 * RRN;
        k_fill_ms<<<TPE(3 * RRN), 256>>>(p_rm, p_rs, 3 * RRN);
        cudaMemsetAsync(p_rtri, 0, RRN * RHD * sizeof(float), 0);
        k_lgat_p1<<<TPE(LGEN), 256>>>(lg_tri, lg_tri + LGEN, tri_val, mi, mj, LGEN);
        k_lgat_p2<<<TPE(LGEN), 256>>>(lg_tri, lg_tri + LGEN, tri_val, mi, mj, si, sj, LGEN);
        k_lgat_p3<<<TPE(LGEN), 256>>>(lg_tri, lg_tri + LGEN, tri_val, mi, si, mj, sj, m3, p_lt, LGEN);
        k_lgat_p4<<<TPE(LGEN), 256>>>(lg_tri, p_lt, m3, s3, p_lp, LGEN);
        k_lgat_p5<<<WPE(LGEN), 256>>>(lg_tri, lg_tri + LGEN, p_lp, s3, rel_tri1, p_rtri, LGEN);
        k_relu<<<TPE(RRN * RHD), 256>>>(p_rtri, RRN * RHD);
    }
    // ---- relation highway + projections ----
    k_gemm<<<gRel, 256, smemR>>>(p_rmerge, hwr_w, p_rgate, RRN, RHD, RHD);
    k_highway_r<<<TPE(RRN * RHD), 256>>>(p_rgate, hwr_b, p_rmerge, p_rtri, p_xr, RRN * RHD, RHD);
    k_rcar<<<WPE(RRN), 256>>>(p_rmerge, p_rtri, gat_ar, p_rcar);

    // ---- GAT over edge_index_all (x = p_xw) ----
    k_node_dots2<<<WPE(NN), 256>>>(p_xw, EHID, EHID, gat_ai, gat_aj, p_na, p_nb, NN);
    k_fill_ms<<<TPE(NN), 256>>>(p_m1, p_s1, NN);
    k_gat_p1<<<TPE(NE2), 256>>>(ei_all, ei_all + NE2, rel_all, p_na, p_nb, p_rcar, p_e1, p_m1, NE2);
    k_seg_exp<<<TPE(NE2), 256>>>(ei_all + NE2, p_e1, p_m1, p_s1, NE2);
    k_gat_csr<<<WPE(NN), 256>>>(p_off, p_csrj, p_csre, p_e1, p_s1, p_xw, out);

    // ---- gat_r_to_e ----
    k_node_dots2<<<WPE(NN), 256>>>(out, OUTW, 600, g2e_ah, g2e_at, p_na, p_nb, NN);
    k_dot_rows<<<WPE(RRN), 256>>>(p_xr, RHD, RHD, g2e_ar, p_rcar, RRN);
    k_fill_ms<<<TPE(NN), 256>>>(p_m1, p_s1, NN);
    k_fill_ms<<<TPE(NN), 256>>>(p_m2, p_s2, NN);
    k_g2e_p1<<<TPE(NE1), 256>>>(ei, ei + NE1, rel, p_na, p_nb, p_rcar, p_e1, p_e2, p_m1, p_m2, NE1);
    k_seg_exp<<<TPE(NE1), 256>>>(ei, p_e1, p_m1, p_s1, NE1);
    k_seg_exp<<<TPE(NE1), 256>>>(ei + NE1, p_e2, p_m2, p_s2, NE1);
    k_g2e_p3<<<WPE(NE1), 256>>>(ei, ei + NE1, rel, p_e1, p_s1, p_e2, p_s2, p_xr, out, NE1);
}